// round 13
// baseline (speedup 1.0000x reference)
#include <cuda_runtime.h>
#include <cuda_bf16.h>
#include <stdint.h>

// Problem constants
#define B_  2
#define S_  2048
#define D_  1024
#define H_  16
#define DK_ 64
#define M_  (B_ * S_)

#define QSCALE (0.125f * 1.44269504088896340736f)

// ---------------------------------------------------------------------------
// Scratch (device globals — no allocations allowed)
// ---------------------------------------------------------------------------
__device__ __nv_bfloat16 g_Ah[3][M_ * D_];   // activation hi (slot 0 reused for ctx)
__device__ __nv_bfloat16 g_Al[3][M_ * D_];   // activation lo
__device__ __nv_bfloat16 g_Wh[4][D_ * D_];   // weight hi, TRANSPOSED [N][K]
__device__ __nv_bfloat16 g_Wl[4][D_ * D_];   // weight lo

__device__ __nv_bfloat16 g_qh[B_ * H_ * S_ * DK_];  // [bh][s][dk], pre-scaled
__device__ __nv_bfloat16 g_ql[B_ * H_ * S_ * DK_];
__device__ __nv_bfloat16 g_kh[B_ * H_ * S_ * DK_];
__device__ __nv_bfloat16 g_kl[B_ * H_ * S_ * DK_];
__device__ __nv_bfloat16 g_vh[B_ * H_ * DK_ * S_];  // TRANSPOSED [bh][dk][s]
__device__ __nv_bfloat16 g_vl[B_ * H_ * DK_ * S_];

// ---------------------------------------------------------------------------
// Helpers
// ---------------------------------------------------------------------------
__device__ __forceinline__ void split1(float x, __nv_bfloat16& h, __nv_bfloat16& l) {
    h = __float2bfloat16_rn(x);
    l = __float2bfloat16_rn(x - __bfloat162float(h));
}

__device__ __forceinline__ uint32_t pack_bf16(float lo, float hi) {
    uint32_t r;
    asm("cvt.rn.bf16x2.f32 %0, %1, %2;" : "=r"(r) : "f"(hi), "f"(lo));
    return r;
}

__device__ __forceinline__ float fast_exp2(float x) {
    float r;
    asm("ex2.approx.f32 %0, %1;" : "=f"(r) : "f"(x));
    return r;
}

__device__ __forceinline__ void mma16816(float* c, const uint32_t* a, const uint32_t* b)
{
    asm("mma.sync.aligned.m16n8k16.row.col.f32.bf16.bf16.f32 "
        "{%0,%1,%2,%3},{%4,%5,%6,%7},{%8,%9},{%0,%1,%2,%3};"
        : "+f"(c[0]), "+f"(c[1]), "+f"(c[2]), "+f"(c[3])
        : "r"(a[0]), "r"(a[1]), "r"(a[2]), "r"(a[3]), "r"(b[0]), "r"(b[1]));
}

__device__ __forceinline__ void ldsm4(uint32_t* r, uint32_t addr)
{
    asm volatile("ldmatrix.sync.aligned.m8n8.x4.shared.b16 {%0,%1,%2,%3}, [%4];"
        : "=r"(r[0]), "=r"(r[1]), "=r"(r[2]), "=r"(r[3]) : "r"(addr));
}

__device__ __forceinline__ uint32_t smem_u32(const void* p) {
    return (uint32_t)__cvta_generic_to_shared(p);
}
__device__ __forceinline__ void cpa16(uint32_t d, const void* s) {
    asm volatile("cp.async.cg.shared.global [%0], [%1], 16;" :: "r"(d), "l"(s));
}
__device__ __forceinline__ void cp_commit() { asm volatile("cp.async.commit_group;"); }
__device__ __forceinline__ void cp_wait0()  { asm volatile("cp.async.wait_group 0;"); }
__device__ __forceinline__ void cp_wait1()  { asm volatile("cp.async.wait_group 1;"); }

// ---------------------------------------------------------------------------
// Split kernels (unchanged)
// ---------------------------------------------------------------------------
__global__ __launch_bounds__(256)
void split_act_all(const float* __restrict__ q, const float* __restrict__ k,
                   const float* __restrict__ v)
{
    const int z = blockIdx.y;
    const float* src = (z == 0) ? q : (z == 1) ? k : v;
    const int i = blockIdx.x * 256 + threadIdx.x;
    float4 val = reinterpret_cast<const float4*>(src)[i];
    __nv_bfloat16 h0, h1, h2, h3, l0, l1, l2, l3;
    split1(val.x, h0, l0); split1(val.y, h1, l1);
    split1(val.z, h2, l2); split1(val.w, h3, l3);
    uint2 hp, lp;
    hp.x = ((uint32_t)__bfloat16_as_ushort(h1) << 16) | __bfloat16_as_ushort(h0);
    hp.y = ((uint32_t)__bfloat16_as_ushort(h3) << 16) | __bfloat16_as_ushort(h2);
    lp.x = ((uint32_t)__bfloat16_as_ushort(l1) << 16) | __bfloat16_as_ushort(l0);
    lp.y = ((uint32_t)__bfloat16_as_ushort(l3) << 16) | __bfloat16_as_ushort(l2);
    reinterpret_cast<uint2*>(g_Ah[z])[i] = hp;
    reinterpret_cast<uint2*>(g_Al[z])[i] = lp;
}

__global__ __launch_bounds__(256)
void split_wt_all(const float* __restrict__ Wq, const float* __restrict__ Wk,
                  const float* __restrict__ Wv, const float* __restrict__ Wo)
{
    __shared__ float tile[32][33];
    const int z = blockIdx.z;
    const float* W = (z == 0) ? Wq : (z == 1) ? Wk : (z == 2) ? Wv : Wo;
    const int tx = threadIdx.x;
    const int ty = threadIdx.y;
    const int n0 = blockIdx.x * 32;
    const int k0 = blockIdx.y * 32;
#pragma unroll
    for (int i = 0; i < 32; i += 8)
        tile[ty + i][tx] = W[(size_t)(k0 + ty + i) * D_ + n0 + tx];
    __syncthreads();
#pragma unroll
    for (int i = 0; i < 32; i += 8) {
        float v = tile[tx][ty + i];
        __nv_bfloat16 h, l;
        split1(v, h, l);
        size_t idx = (size_t)(n0 + ty + i) * D_ + k0 + tx;
        g_Wh[z][idx] = h;
        g_Wl[z][idx] = l;
    }
}

// ---------------------------------------------------------------------------
// Tensor-core GEMM (bf16x3): 256x128 block tile, 512 threads,
// THREE-stage cp.async pipeline (2 tiles in flight) to cover L2 latency.
// ---------------------------------------------------------------------------
#define TSTR 40
#define ASZ (256 * TSTR)
#define BSZ (128 * TSTR)
#define STAGE_E (2 * ASZ + 2 * BSZ)
#define NSTAGE 3

template <int MODE>
__global__ __launch_bounds__(512)
void gemm_tc(const float* __restrict__ bias0, const float* __restrict__ bias1,
             const float* __restrict__ bias2, float* __restrict__ Cout)
{
    extern __shared__ __nv_bfloat16 sm[];

    const int z = (MODE == 1) ? blockIdx.z : 0;
    const __nv_bfloat16* Ah = g_Ah[z];
    const __nv_bfloat16* Al = g_Al[z];
    const __nv_bfloat16* Wh = g_Wh[(MODE == 0) ? 3 : z];
    const __nv_bfloat16* Wl = g_Wl[(MODE == 0) ? 3 : z];
    const float* bias = (MODE == 0) ? bias0 : (z == 0) ? bias0 : (z == 1) ? bias1 : bias2;
    const float oscale = (MODE == 1 && z == 0) ? QSCALE : 1.0f;

    const int tid = threadIdx.x;
    const int bm = blockIdx.y * 256;
    const int bn = blockIdx.x * 128;

    const int lane = tid & 31;
    const int wid  = tid >> 5;
    const int wm   = wid & 7;
    const int wn   = wid >> 3;
    const int g    = lane >> 2;
    const int tg   = lane & 3;

    const int ar   = tid >> 1;
    const int acol = (tid & 1) * 16;
    const int br   = tid >> 2;
    const int bcol = (tid & 3) * 8;

    const uint32_t smb = smem_u32(sm);

    const uint32_t offA = (uint32_t)(((lane & 7) + (((lane >> 3) & 1) * 8)) * TSTR
                                     + (lane >> 4) * 8) * 2;
    const uint32_t offB = (uint32_t)(((lane & 7) + ((lane >> 4) * 8)) * TSTR
                                     + ((lane >> 3) & 1) * 8) * 2;

    auto issue = [&](int kt) {
        const int st = kt % NSTAGE;
        const size_t colA = (size_t)kt * 32 + acol;
        const size_t colB = (size_t)kt * 32 + bcol;
        const size_t a0 = (size_t)(bm + ar) * D_ + colA;
        const size_t b0 = (size_t)(bn + br) * D_ + colB;
        const uint32_t base = smb + (uint32_t)st * (STAGE_E * 2);
        const uint32_t sA = base + (uint32_t)(ar * TSTR + acol) * 2;
        const uint32_t sB = base + (uint32_t)(2 * ASZ + br * TSTR + bcol) * 2;
        cpa16(sA,                 Ah + a0);
        cpa16(sA + 16,            Ah + a0 + 8);
        cpa16(sA + ASZ * 2,       Al + a0);
        cpa16(sA + ASZ * 2 + 16,  Al + a0 + 8);
        cpa16(sB,                 Wh + b0);
        cpa16(sB + BSZ * 2,       Wl + b0);
        cp_commit();
    };

    float acc[2][8][4];
#pragma unroll
    for (int mt = 0; mt < 2; mt++)
#pragma unroll
        for (int nt = 0; nt < 8; nt++)
#pragma unroll
            for (int i = 0; i < 4; i++) acc[mt][nt][i] = 0.f;

    issue(0);
    issue(1);

    const int NT = D_ / 32;
    for (int kt = 0; kt < NT; kt++) {
        // need group kt complete; keep group kt+1 in flight
        if (kt == NT - 1) cp_wait0(); else cp_wait1();
        __syncthreads();
        if (kt + 2 < NT) issue(kt + 2);

        const uint32_t base = smb + (uint32_t)(kt % NSTAGE) * (STAGE_E * 2);
        const uint32_t bAh = base;
        const uint32_t bAl = base + ASZ * 2;
        const uint32_t bBh = base + 2 * ASZ * 2;
        const uint32_t bBl = base + (2 * ASZ + BSZ) * 2;

#pragma unroll
        for (int kk = 0; kk < 32; kk += 16) {
            uint32_t ah[2][4], al[2][4];
#pragma unroll
            for (int mt = 0; mt < 2; mt++) {
                const uint32_t ro = (uint32_t)((wm * 32 + mt * 16) * TSTR + kk) * 2;
                ldsm4(ah[mt], bAh + ro + offA);
                ldsm4(al[mt], bAl + ro + offA);
            }
#pragma unroll
            for (int ntp = 0; ntp < 4; ntp++) {
                const uint32_t ro = (uint32_t)((wn * 64 + ntp * 16) * TSTR + kk) * 2;
                uint32_t bh4[4], bl4[4];
                ldsm4(bh4, bBh + ro + offB);
                ldsm4(bl4, bBl + ro + offB);
                mma16816(acc[0][2 * ntp],     ah[0], &bh4[0]);
                mma16816(acc[1][2 * ntp],     ah[1], &bh4[0]);
                mma16816(acc[0][2 * ntp + 1], ah[0], &bh4[2]);
                mma16816(acc[1][2 * ntp + 1], ah[1], &bh4[2]);
                mma16816(acc[0][2 * ntp],     ah[0], &bl4[0]);
                mma16816(acc[1][2 * ntp],     ah[1], &bl4[0]);
                mma16816(acc[0][2 * ntp + 1], ah[0], &bl4[2]);
                mma16816(acc[1][2 * ntp + 1], ah[1], &bl4[2]);
                mma16816(acc[0][2 * ntp],     al[0], &bh4[0]);
                mma16816(acc[1][2 * ntp],     al[1], &bh4[0]);
                mma16816(acc[0][2 * ntp + 1], al[0], &bh4[2]);
                mma16816(acc[1][2 * ntp + 1], al[1], &bh4[2]);
            }
        }
    }

#pragma unroll
    for (int mt = 0; mt < 2; mt++) {
#pragma unroll
        for (int nt = 0; nt < 8; nt++) {
            const int col = bn + wn * 64 + nt * 8 + tg * 2;
            const float b0 = bias[col], b1 = bias[col + 1];
#pragma unroll
            for (int half = 0; half < 2; half++) {
                const int row = bm + wm * 32 + mt * 16 + g + half * 8;
                float vx = acc[mt][nt][half * 2 + 0] + b0;
                float vy = acc[mt][nt][half * 2 + 1] + b1;
                if (MODE == 0) {
                    *reinterpret_cast<float2*>(Cout + (size_t)row * D_ + col) =
                        make_float2(vx, vy);
                } else {
                    vx *= oscale; vy *= oscale;
                    __nv_bfloat16 hx, lx, hy, ly;
                    split1(vx, hx, lx);
                    split1(vy, hy, ly);
                    const int b  = row >> 11;
                    const int s  = row & (S_ - 1);
                    const int h  = col >> 6;
                    const int dk = col & (DK_ - 1);
                    const size_t bh = (size_t)b * H_ + h;
                    if (z == 0 || z == 1) {
                        const size_t idx = (bh * S_ + s) * DK_ + dk;
                        uint32_t hp = ((uint32_t)__bfloat16_as_ushort(hy) << 16) |
                                      __bfloat16_as_ushort(hx);
                        uint32_t lp = ((uint32_t)__bfloat16_as_ushort(ly) << 16) |
                                      __bfloat16_as_ushort(lx);
                        __nv_bfloat16* dh = (z == 0) ? g_qh : g_kh;
                        __nv_bfloat16* dl = (z == 0) ? g_ql : g_kl;
                        *reinterpret_cast<uint32_t*>(dh + idx) = hp;
                        *reinterpret_cast<uint32_t*>(dl + idx) = lp;
                    } else {
                        const size_t idx = (bh * DK_ + dk) * S_ + s;
                        g_vh[idx]      = hx;
                        g_vh[idx + S_] = hy;
                        g_vl[idx]      = lx;
                        g_vl[idx + S_] = ly;
                    }
                }
            }
        }
    }
}

// ---------------------------------------------------------------------------
// Tensor-core flash attention (bf16x3) — byte-identical to passing R12.
// ---------------------------------------------------------------------------
#define KSTR 72
#define ASTAGE (64 * KSTR)

__global__ __launch_bounds__(256, 2)
void attn_tc(const int* __restrict__ mask)
{
    extern __shared__ __nv_bfloat16 sm[];
    float* smadd = reinterpret_cast<float*>(sm + 2 * 4 * ASTAGE);

    const int bh = blockIdx.y;
    const int b  = bh >> 4;
    const int h  = bh & 15;
    const int tid  = threadIdx.x;
    const int lane = tid & 31;
    const int wid  = tid >> 5;
    const int g    = lane >> 2;
    const int tg   = lane & 3;
    const int qrow0 = blockIdx.x * 128 + wid * 16;

    const size_t kbase = (size_t)bh * S_ * DK_;
    const size_t vbase = (size_t)bh * DK_ * S_;
    const int lr = tid >> 2;
    const int lc = (tid & 3) * 16;

    const uint32_t smb = smem_u32(sm);
    const uint32_t soff = (uint32_t)(lr * KSTR + lc) * 2;
    const uint32_t offB = (uint32_t)(((lane & 7) + ((lane >> 4) * 8)) * KSTR
                                     + ((lane >> 3) & 1) * 8) * 2;

    auto issue = [&](int kt, int st) {
        const size_t koff = kbase + (size_t)(kt + lr) * DK_ + lc;
        const size_t voff = vbase + (size_t)lr * S_ + kt + lc;
        const uint32_t base = smb + (uint32_t)st * (4 * ASTAGE * 2);
        cpa16(base + soff,                       g_kh + koff);
        cpa16(base + soff + 16,                  g_kh + koff + 8);
        cpa16(base + ASTAGE * 2 + soff,          g_kl + koff);
        cpa16(base + ASTAGE * 2 + soff + 16,     g_kl + koff + 8);
        cpa16(base + 2 * ASTAGE * 2 + soff,      g_vh + voff);
        cpa16(base + 2 * ASTAGE * 2 + soff + 16, g_vh + voff + 8);
        cpa16(base + 3 * ASTAGE * 2 + soff,      g_vl + voff);
        cpa16(base + 3 * ASTAGE * 2 + soff + 16, g_vl + voff + 8);
        cp_commit();
    };

    issue(0, 0);

#pragma unroll
    for (int i = 0; i < S_ / 256; i++)
        smadd[tid + i * 256] = (mask[b * S_ + tid + i * 256] == 0) ? -1e30f : 0.f;

    const size_t qoff = (size_t)bh * S_ * DK_;
    uint32_t aqh[4][4], aql[4][4];
#pragma unroll
    for (int ks = 0; ks < 4; ks++) {
        const int c0 = ks * 16 + 2 * tg;
        const size_t r0 = qoff + (size_t)(qrow0 + g) * DK_;
        const size_t r1 = qoff + (size_t)(qrow0 + g + 8) * DK_;
        aqh[ks][0] = *reinterpret_cast<const uint32_t*>(g_qh + r0 + c0);
        aqh[ks][1] = *reinterpret_cast<const uint32_t*>(g_qh + r1 + c0);
        aqh[ks][2] = *reinterpret_cast<const uint32_t*>(g_qh + r0 + c0 + 8);
        aqh[ks][3] = *reinterpret_cast<const uint32_t*>(g_qh + r1 + c0 + 8);
        aql[ks][0] = *reinterpret_cast<const uint32_t*>(g_ql + r0 + c0);
        aql[ks][1] = *reinterpret_cast<const uint32_t*>(g_ql + r1 + c0);
        aql[ks][2] = *reinterpret_cast<const uint32_t*>(g_ql + r0 + c0 + 8);
        aql[ks][3] = *reinterpret_cast<const uint32_t*>(g_ql + r1 + c0 + 8);
    }

    float accO[8][4];
#pragma unroll
    for (int i = 0; i < 8; i++)
#pragma unroll
        for (int j = 0; j < 4; j++) accO[i][j] = 0.f;

    float sum0 = 0.f, sum1 = 0.f;

    const int NTILES = S_ / 64;
    for (int t = 0; t < NTILES; t++) {
        const int kt = t * 64;
        cp_wait0();
        __syncthreads();
        if (t + 1 < NTILES) issue(kt + 64, (t + 1) & 1);

        const uint32_t bKh = smb + (uint32_t)(t & 1) * (4 * ASTAGE * 2);
        const uint32_t bKl = bKh + ASTAGE * 2;
        const uint32_t bVh = bKh + 2 * ASTAGE * 2;
        const uint32_t bVl = bKh + 3 * ASTAGE * 2;

        // ---- S = Q K^T (pure tensor phase) ----
        float acc[8][4];
#pragma unroll
        for (int i = 0; i < 8; i++)
#pragma unroll
            for (int j = 0; j < 4; j++) acc[i][j] = 0.f;

#pragma unroll
        for (int ks = 0; ks < 4; ks++)
#pragma unroll
            for (int ntp = 0; ntp < 4; ntp++) {
                const uint32_t ro = (uint32_t)(ntp * 16 * KSTR + ks * 16) * 2;
                uint32_t kh4[4], kl4[4];
                ldsm4(kh4, bKh + ro + offB);
                ldsm4(kl4, bKl + ro + offB);
                mma16816(acc[2 * ntp],     aqh[ks], &kh4[0]);
                mma16816(acc[2 * ntp + 1], aqh[ks], &kh4[2]);
                mma16816(acc[2 * ntp],     aqh[ks], &kl4[0]);
                mma16816(acc[2 * ntp + 1], aqh[ks], &kl4[2]);
                mma16816(acc[2 * ntp],     aql[ks], &kh4[0]);
                mma16816(acc[2 * ntp + 1], aql[ks], &kh4[2]);
            }

        // ---- fused per-group softmax + PV (R8 packing order) ----
#pragma unroll
        for (int kb2 = 0; kb2 < 4; kb2++) {
            uint32_t ph[4], pl[4];
#pragma unroll
            for (int half = 0; half < 2; half++) {
                const int nt = 2 * kb2 + half;
                const float ma = smadd[kt + nt * 8 + 2 * tg];
                const float mb = smadd[kt + nt * 8 + 2 * tg + 1];
                const float p0 = fast_exp2(acc[nt][0] + ma);
                const float p1 = fast_exp2(acc[nt][1] + mb);
                const float p2 = fast_exp2(acc[nt][2] + ma);
                const float p3 = fast_exp2(acc[nt][3] + mb);
                sum0 += p0 + p1;
                sum1 += p2 + p3;
                const uint32_t h01 = pack_bf16(p0, p1);
                const uint32_t h23 = pack_bf16(p2, p3);
                const float q0 = p0 - __uint_as_float(h01 << 16);
                const float q1 = p1 - __uint_as_float(h01 & 0xffff0000u);
                const float q2 = p2 - __uint_as_float(h23 << 16);
                const float q3 = p3 - __uint_as_float(h23 & 0xffff0000u);
                ph[2 * half + 0] = h01;
                ph[2 * half + 1] = h23;
                pl[2 * half + 0] = pack_bf16(q0, q1);
                pl[2 * half + 1] = pack_bf16(q2, q3);
            }
#pragma unroll
            for (int ntp = 0; ntp < 4; ntp++) {
                const uint32_t ro = (uint32_t)(ntp * 16 * KSTR + kb2 * 16) * 2;
                uint32_t vh4[4], vl4[4];
                ldsm4(vh4, bVh + ro + offB);
                ldsm4(vl4, bVl + ro + offB);
                mma16816(accO[2 * ntp],     ph, &vh4[0]);
                mma16816(accO[2 * ntp + 1], ph, &vh4[2]);
                mma16816(accO[2 * ntp],     ph, &vl4[0]);
                mma16816(accO[2 * ntp + 1], ph, &vl4[2]);
                mma16816(accO[2 * ntp],     pl, &vh4[0]);
                mma16816(accO[2 * ntp + 1], pl, &vh4[2]);
            }
        }
    }

    sum0 += __shfl_xor_sync(0xffffffffu, sum0, 1);
    sum0 += __shfl_xor_sync(0xffffffffu, sum0, 2);
    sum1 += __shfl_xor_sync(0xffffffffu, sum1, 1);
    sum1 += __shfl_xor_sync(0xffffffffu, sum1, 2);

    const float i0 = 1.f / sum0;
    const float i1 = 1.f / sum1;
    const size_t orow0 = ((size_t)b * S_ + qrow0 + g) * D_ + h * DK_;
    const size_t orow1 = orow0 + (size_t)8 * D_;
#pragma unroll
    for (int nt2 = 0; nt2 < 8; nt2++) {
        const int dk = nt2 * 8 + 2 * tg;
        float vx0 = accO[nt2][0] * i0, vy0 = accO[nt2][1] * i0;
        float vx1 = accO[nt2][2] * i1, vy1 = accO[nt2][3] * i1;
        __nv_bfloat16 hx, lx, hy, ly;
        split1(vx0, hx, lx); split1(vy0, hy, ly);
        *reinterpret_cast<uint32_t*>(g_Ah[0] + orow0 + dk) =
            ((uint32_t)__bfloat16_as_ushort(hy) << 16) | __bfloat16_as_ushort(hx);
        *reinterpret_cast<uint32_t*>(g_Al[0] + orow0 + dk) =
            ((uint32_t)__bfloat16_as_ushort(ly) << 16) | __bfloat16_as_ushort(lx);
        split1(vx1, hx, lx); split1(vy1, hy, ly);
        *reinterpret_cast<uint32_t*>(g_Ah[0] + orow1 + dk) =
            ((uint32_t)__bfloat16_as_ushort(hy) << 16) | __bfloat16_as_ushort(hx);
        *reinterpret_cast<uint32_t*>(g_Al[0] + orow1 + dk) =
            ((uint32_t)__bfloat16_as_ushort(ly) << 16) | __bfloat16_as_ushort(lx);
    }
}

// ---------------------------------------------------------------------------
// Launch
// ---------------------------------------------------------------------------
#define GEMM_SMEM (NSTAGE * STAGE_E * 2)             // 184320 B
#define ATTN_SMEM (2 * 4 * ASTAGE * 2 + S_ * 4)

extern "C" void kernel_launch(void* const* d_in, const int* in_sizes, int n_in,
                              void* d_out, int out_size)
{
    const float* query = (const float*)d_in[0];
    const float* key   = (const float*)d_in[1];
    const float* value = (const float*)d_in[2];
    const int*   mask  = (const int*)  d_in[3];
    const float* Wq = (const float*)d_in[4];
    const float* bq = (const float*)d_in[5];
    const float* Wk = (const float*)d_in[6];
    const float* bk = (const float*)d_in[7];
    const float* Wv = (const float*)d_in[8];
    const float* bv = (const float*)d_in[9];
    const float* Wo = (const float*)d_in[10];
    const float* bo = (const float*)d_in[11];
    float* out = (float*)d_out;

    cudaFuncSetAttribute(gemm_tc<1>, cudaFuncAttributeMaxDynamicSharedMemorySize, GEMM_SMEM);
    cudaFuncSetAttribute(gemm_tc<0>, cudaFuncAttributeMaxDynamicSharedMemorySize, GEMM_SMEM);
    cudaFuncSetAttribute(attn_tc,    cudaFuncAttributeMaxDynamicSharedMemorySize, ATTN_SMEM);

    dim3 wtg(D_ / 32, D_ / 32, 4);
    split_wt_all<<<wtg, dim3(32, 8)>>>(Wq, Wk, Wv, Wo);
    dim3 sag((M_ * D_ / 4) / 256, 3);
    split_act_all<<<sag, 256>>>(query, key, value);

    dim3 gqkv(D_ / 128, M_ / 256, 3);
    gemm_tc<1><<<gqkv, 512, GEMM_SMEM>>>(bq, bk, bv, nullptr);

    dim3 agrid(S_ / 128, B_ * H_);
    attn_tc<<<agrid, 256, ATTN_SMEM>>>(mask);

    dim3 gout(D_ / 128, M_ / 256);
    gemm_tc<0><<<gout, 512, GEMM_SMEM>>>(bo, nullptr, nullptr, out);
}

// round 14
// speedup vs baseline: 1.1577x; 1.1577x over previous
#include <cuda_runtime.h>
#include <cuda_bf16.h>
#include <stdint.h>

// Problem constants
#define B_  2
#define S_  2048
#define D_  1024
#define H_  16
#define DK_ 64
#define M_  (B_ * S_)

#define QSCALE (0.125f * 1.44269504088896340736f)

// ---------------------------------------------------------------------------
// Scratch (device globals — no allocations allowed)
// g_Ah/g_Al/g_Wh/g_Wl are stored K-CHUNK-TILE-MAJOR with sub-chunk swizzle:
//   elem (row, k) -> ((k>>5)*ROWS + row)*32 + (((k&31)>>3) ^ ((row>>1)&3))*8 + (k&7)
// so a GEMM K-tile slice (rows r0..r0+R, one 32-k chunk) is CONTIGUOUS and
// loadable with a single cp.async.bulk, while ldmatrix stays conflict-free.
// ---------------------------------------------------------------------------
__device__ __nv_bfloat16 g_Ah[3][M_ * D_];   // activation hi (slot 0 reused for ctx)
__device__ __nv_bfloat16 g_Al[3][M_ * D_];   // activation lo
__device__ __nv_bfloat16 g_Wh[4][D_ * D_];   // weight hi, [N][K] tile-major
__device__ __nv_bfloat16 g_Wl[4][D_ * D_];   // weight lo

__device__ __nv_bfloat16 g_qh[B_ * H_ * S_ * DK_];  // [bh][s][dk], pre-scaled
__device__ __nv_bfloat16 g_ql[B_ * H_ * S_ * DK_];
__device__ __nv_bfloat16 g_kh[B_ * H_ * S_ * DK_];
__device__ __nv_bfloat16 g_kl[B_ * H_ * S_ * DK_];
__device__ __nv_bfloat16 g_vh[B_ * H_ * DK_ * S_];  // TRANSPOSED [bh][dk][s]
__device__ __nv_bfloat16 g_vl[B_ * H_ * DK_ * S_];

// ---------------------------------------------------------------------------
// Helpers
// ---------------------------------------------------------------------------
__device__ __forceinline__ size_t tm_idx(int row, int k, int nrows) {
    const int chunk = k >> 5;
    const int cc = k & 31;
    const int sc = (cc >> 3) ^ ((row >> 1) & 3);
    return ((size_t)chunk * nrows + row) * 32 + sc * 8 + (cc & 7);
}

__device__ __forceinline__ void split1(float x, __nv_bfloat16& h, __nv_bfloat16& l) {
    h = __float2bfloat16_rn(x);
    l = __float2bfloat16_rn(x - __bfloat162float(h));
}

__device__ __forceinline__ uint32_t pack_bf16(float lo, float hi) {
    uint32_t r;
    asm("cvt.rn.bf16x2.f32 %0, %1, %2;" : "=r"(r) : "f"(hi), "f"(lo));
    return r;
}

__device__ __forceinline__ float fast_exp2(float x) {
    float r;
    asm("ex2.approx.f32 %0, %1;" : "=f"(r) : "f"(x));
    return r;
}

__device__ __forceinline__ void mma16816(float* c, const uint32_t* a, const uint32_t* b)
{
    asm("mma.sync.aligned.m16n8k16.row.col.f32.bf16.bf16.f32 "
        "{%0,%1,%2,%3},{%4,%5,%6,%7},{%8,%9},{%0,%1,%2,%3};"
        : "+f"(c[0]), "+f"(c[1]), "+f"(c[2]), "+f"(c[3])
        : "r"(a[0]), "r"(a[1]), "r"(a[2]), "r"(a[3]), "r"(b[0]), "r"(b[1]));
}

__device__ __forceinline__ void ldsm4(uint32_t* r, uint32_t addr)
{
    asm volatile("ldmatrix.sync.aligned.m8n8.x4.shared.b16 {%0,%1,%2,%3}, [%4];"
        : "=r"(r[0]), "=r"(r[1]), "=r"(r[2]), "=r"(r[3]) : "r"(addr));
}

__device__ __forceinline__ uint32_t smem_u32(const void* p) {
    return (uint32_t)__cvta_generic_to_shared(p);
}
__device__ __forceinline__ void cpa16(uint32_t d, const void* s) {
    asm volatile("cp.async.cg.shared.global [%0], [%1], 16;" :: "r"(d), "l"(s));
}
__device__ __forceinline__ void cp_commit() { asm volatile("cp.async.commit_group;"); }
__device__ __forceinline__ void cp_wait0()  { asm volatile("cp.async.wait_group 0;"); }

__device__ __forceinline__ void bulk_g2s(uint32_t dst, const void* src,
                                         uint32_t bytes, uint32_t mbar)
{
    asm volatile("cp.async.bulk.shared::cta.global.mbarrier::complete_tx::bytes "
                 "[%0], [%1], %2, [%3];"
        :: "r"(dst), "l"(src), "r"(bytes), "r"(mbar) : "memory");
}

#define MBAR_INIT(mbar, count) \
    asm volatile("mbarrier.init.shared.b64 [%0], %1;" \
        :: "r"((uint32_t)(mbar)), "r"((uint32_t)(count)) : "memory")
#define MBAR_EXPECT_TX(mbar, tx) \
    asm volatile("mbarrier.arrive.expect_tx.shared.b64 _, [%0], %1;" \
        :: "r"((uint32_t)(mbar)), "r"((uint32_t)(tx)) : "memory")
#define MBAR_WAIT(mbar, parity) do { \
    uint32_t _m = (uint32_t)(mbar); uint32_t _p = (uint32_t)(parity); uint32_t _d; \
    asm volatile("{\n\t.reg .pred p;\n\t" \
        "mbarrier.try_wait.parity.acquire.cta.shared::cta.b64 p, [%1], %2;\n\t" \
        "selp.b32 %0, 1, 0, p;\n\t}" : "=r"(_d) : "r"(_m), "r"(_p) : "memory"); \
    if (!_d) { \
        asm volatile("{\n\t.reg .pred P1;\n\t" \
            "WL_%=:\n\t" \
            "mbarrier.try_wait.parity.acquire.cta.shared::cta.b64 P1, [%0], %1, 0x989680;\n\t" \
            "@P1 bra.uni WD_%=;\n\tbra.uni WL_%=;\n\tWD_%=:\n\t}" \
            :: "r"(_m), "r"(_p) : "memory"); \
    } \
} while (0)

// ---------------------------------------------------------------------------
// Split kernels — write the tile-major swizzled layout.
// ---------------------------------------------------------------------------
__global__ __launch_bounds__(256)
void split_act_all(const float* __restrict__ q, const float* __restrict__ k,
                   const float* __restrict__ v)
{
    const int z = blockIdx.y;
    const float* src = (z == 0) ? q : (z == 1) ? k : v;
    const int i = blockIdx.x * 256 + threadIdx.x;        // float4 index
    const int m  = i >> 8;                               // D_/4 = 256 per row
    const int k0 = (i & 255) * 4;
    float4 val = reinterpret_cast<const float4*>(src)[i];
    __nv_bfloat16 h0, h1, h2, h3, l0, l1, l2, l3;
    split1(val.x, h0, l0); split1(val.y, h1, l1);
    split1(val.z, h2, l2); split1(val.w, h3, l3);
    uint2 hp, lp;
    hp.x = ((uint32_t)__bfloat16_as_ushort(h1) << 16) | __bfloat16_as_ushort(h0);
    hp.y = ((uint32_t)__bfloat16_as_ushort(h3) << 16) | __bfloat16_as_ushort(h2);
    lp.x = ((uint32_t)__bfloat16_as_ushort(l1) << 16) | __bfloat16_as_ushort(l0);
    lp.y = ((uint32_t)__bfloat16_as_ushort(l3) << 16) | __bfloat16_as_ushort(l2);
    const size_t pos = tm_idx(m, k0, M_);
    *reinterpret_cast<uint2*>(g_Ah[z] + pos) = hp;
    *reinterpret_cast<uint2*>(g_Al[z] + pos) = lp;
}

__global__ __launch_bounds__(256)
void split_wt_all(const float* __restrict__ Wq, const float* __restrict__ Wk,
                  const float* __restrict__ Wv, const float* __restrict__ Wo)
{
    __shared__ float tile[32][33];
    const int z = blockIdx.z;
    const float* W = (z == 0) ? Wq : (z == 1) ? Wk : (z == 2) ? Wv : Wo;
    const int tx = threadIdx.x;
    const int ty = threadIdx.y;
    const int n0 = blockIdx.x * 32;
    const int k0 = blockIdx.y * 32;
#pragma unroll
    for (int i = 0; i < 32; i += 8)
        tile[ty + i][tx] = W[(size_t)(k0 + ty + i) * D_ + n0 + tx];
    __syncthreads();
#pragma unroll
    for (int i = 0; i < 32; i += 8) {
        float v = tile[tx][ty + i];
        __nv_bfloat16 h, l;
        split1(v, h, l);
        const size_t idx = tm_idx(n0 + ty + i, k0 + tx, D_);
        g_Wh[z][idx] = h;
        g_Wl[z][idx] = l;
    }
}

// ---------------------------------------------------------------------------
// Tensor-core GEMM (bf16x3): 256x128 block tile, 512 threads, double-buffered
// via cp.async.bulk (4 bulk ops / K-tile) + mbarrier expect_tx.
// ---------------------------------------------------------------------------
#define STB 49152        // bytes per stage: Ah 16K | Al 16K | Bh 8K | Bl 8K
#define GEMM_SMEM (128 + 2 * STB)

template <int MODE>
__global__ __launch_bounds__(512)
void gemm_tc(const float* __restrict__ bias0, const float* __restrict__ bias1,
             const float* __restrict__ bias2, float* __restrict__ Cout)
{
    extern __shared__ char smc[];

    const int z = (MODE == 1) ? blockIdx.z : 0;
    const __nv_bfloat16* Ah = g_Ah[z];
    const __nv_bfloat16* Al = g_Al[z];
    const __nv_bfloat16* Wh = g_Wh[(MODE == 0) ? 3 : z];
    const __nv_bfloat16* Wl = g_Wl[(MODE == 0) ? 3 : z];
    const float* bias = (MODE == 0) ? bias0 : (z == 0) ? bias0 : (z == 1) ? bias1 : bias2;
    const float oscale = (MODE == 1 && z == 0) ? QSCALE : 1.0f;

    const int tid = threadIdx.x;
    const int bm = blockIdx.y * 256;
    const int bn = blockIdx.x * 128;

    const int lane = tid & 31;
    const int wid  = tid >> 5;
    const int wm   = wid & 7;
    const int wn   = wid >> 3;
    const int g    = lane >> 2;
    const int tg   = lane & 3;

    const uint32_t smb = smem_u32(smc);
    const uint32_t mb0 = smb, mb1 = smb + 8;

    if (tid == 0) {
        MBAR_INIT(mb0, 1);
        MBAR_INIT(mb1, 1);
    }
    __syncthreads();

    // per-lane ldmatrix row/k-half decomposition
    const int rrA = (lane & 7) + ((lane >> 3) & 1) * 8;
    const int khA = lane >> 4;
    const int rrB = (lane & 7) + (lane >> 4) * 8;
    const int khB = (lane >> 3) & 1;

    auto issue = [&](int t) {
        const uint32_t mb = (t & 1) ? mb1 : mb0;
        const uint32_t base = smb + 128 + (uint32_t)(t & 1) * STB;
        MBAR_EXPECT_TX(mb, STB);
        bulk_g2s(base,         Ah + ((size_t)t * M_ + bm) * 32, 16384, mb);
        bulk_g2s(base + 16384, Al + ((size_t)t * M_ + bm) * 32, 16384, mb);
        bulk_g2s(base + 32768, Wh + ((size_t)t * D_ + bn) * 32, 8192,  mb);
        bulk_g2s(base + 40960, Wl + ((size_t)t * D_ + bn) * 32, 8192,  mb);
    };

    float acc[2][8][4];
#pragma unroll
    for (int mt = 0; mt < 2; mt++)
#pragma unroll
        for (int nt = 0; nt < 8; nt++)
#pragma unroll
            for (int i = 0; i < 4; i++) acc[mt][nt][i] = 0.f;

    if (tid == 0) issue(0);

    const int NT = D_ / 32;
    for (int t = 0; t < NT; t++) {
        if (t + 1 < NT) {
            __syncthreads();                 // stage (t+1)&1 free (compute t-1 done)
            if (tid == 0) issue(t + 1);
        }
        MBAR_WAIT((t & 1) ? mb1 : mb0, (t >> 1) & 1);

        const uint32_t base = smb + 128 + (uint32_t)(t & 1) * STB;
        const uint32_t bAh = base;
        const uint32_t bAl = base + 16384;
        const uint32_t bBh = base + 32768;
        const uint32_t bBl = base + 40960;

#pragma unroll
        for (int kk = 0; kk < 32; kk += 16) {
            uint32_t ah[2][4], al[2][4];
#pragma unroll
            for (int mt = 0; mt < 2; mt++) {
                const int row = wm * 32 + mt * 16 + rrA;
                const int sc = ((kk >> 3) + khA) ^ ((row >> 1) & 3);
                const uint32_t off = (uint32_t)(row * 64 + sc * 16);
                ldsm4(ah[mt], bAh + off);
                ldsm4(al[mt], bAl + off);
            }
#pragma unroll
            for (int ntp = 0; ntp < 4; ntp++) {
                const int row = wn * 64 + ntp * 16 + rrB;
                const int sc = ((kk >> 3) + khB) ^ ((row >> 1) & 3);
                const uint32_t off = (uint32_t)(row * 64 + sc * 16);
                uint32_t bh4[4], bl4[4];
                ldsm4(bh4, bBh + off);
                ldsm4(bl4, bBl + off);
                mma16816(acc[0][2 * ntp],     ah[0], &bh4[0]);
                mma16816(acc[1][2 * ntp],     ah[1], &bh4[0]);
                mma16816(acc[0][2 * ntp + 1], ah[0], &bh4[2]);
                mma16816(acc[1][2 * ntp + 1], ah[1], &bh4[2]);
                mma16816(acc[0][2 * ntp],     ah[0], &bl4[0]);
                mma16816(acc[1][2 * ntp],     ah[1], &bl4[0]);
                mma16816(acc[0][2 * ntp + 1], ah[0], &bl4[2]);
                mma16816(acc[1][2 * ntp + 1], ah[1], &bl4[2]);
                mma16816(acc[0][2 * ntp],     al[0], &bh4[0]);
                mma16816(acc[1][2 * ntp],     al[1], &bh4[0]);
                mma16816(acc[0][2 * ntp + 1], al[0], &bh4[2]);
                mma16816(acc[1][2 * ntp + 1], al[1], &bh4[2]);
            }
        }
    }

    // Epilogue (unchanged destinations)
#pragma unroll
    for (int mt = 0; mt < 2; mt++) {
#pragma unroll
        for (int nt = 0; nt < 8; nt++) {
            const int col = bn + wn * 64 + nt * 8 + tg * 2;
            const float b0 = bias[col], b1 = bias[col + 1];
#pragma unroll
            for (int half = 0; half < 2; half++) {
                const int row = bm + wm * 32 + mt * 16 + g + half * 8;
                float vx = acc[mt][nt][half * 2 + 0] + b0;
                float vy = acc[mt][nt][half * 2 + 1] + b1;
                if (MODE == 0) {
                    *reinterpret_cast<float2*>(Cout + (size_t)row * D_ + col) =
                        make_float2(vx, vy);
                } else {
                    vx *= oscale; vy *= oscale;
                    __nv_bfloat16 hx, lx, hy, ly;
                    split1(vx, hx, lx);
                    split1(vy, hy, ly);
                    const int b  = row >> 11;
                    const int s  = row & (S_ - 1);
                    const int h  = col >> 6;
                    const int dk = col & (DK_ - 1);
                    const size_t bh = (size_t)b * H_ + h;
                    if (z == 0 || z == 1) {
                        const size_t idx = (bh * S_ + s) * DK_ + dk;
                        uint32_t hp = ((uint32_t)__bfloat16_as_ushort(hy) << 16) |
                                      __bfloat16_as_ushort(hx);
                        uint32_t lp = ((uint32_t)__bfloat16_as_ushort(ly) << 16) |
                                      __bfloat16_as_ushort(lx);
                        __nv_bfloat16* dh = (z == 0) ? g_qh : g_kh;
                        __nv_bfloat16* dl = (z == 0) ? g_ql : g_kl;
                        *reinterpret_cast<uint32_t*>(dh + idx) = hp;
                        *reinterpret_cast<uint32_t*>(dl + idx) = lp;
                    } else {
                        const size_t idx = (bh * DK_ + dk) * S_ + s;
                        g_vh[idx]      = hx;
                        g_vh[idx + S_] = hy;
                        g_vl[idx]      = lx;
                        g_vl[idx + S_] = ly;
                    }
                }
            }
        }
    }
}

// ---------------------------------------------------------------------------
// Tensor-core flash attention (bf16x3) — R12 mainloop; epilogue writes the
// ctx in tile-major swizzled layout for the output GEMM.
// ---------------------------------------------------------------------------
#define KSTR 72
#define ASTAGE (64 * KSTR)

__global__ __launch_bounds__(256, 2)
void attn_tc(const int* __restrict__ mask)
{
    extern __shared__ __nv_bfloat16 sm[];
    float* smadd = reinterpret_cast<float*>(sm + 2 * 4 * ASTAGE);

    const int bh = blockIdx.y;
    const int b  = bh >> 4;
    const int h  = bh & 15;
    const int tid  = threadIdx.x;
    const int lane = tid & 31;
    const int wid  = tid >> 5;
    const int g    = lane >> 2;
    const int tg   = lane & 3;
    const int qrow0 = blockIdx.x * 128 + wid * 16;

    const size_t kbase = (size_t)bh * S_ * DK_;
    const size_t vbase = (size_t)bh * DK_ * S_;
    const int lr = tid >> 2;
    const int lc = (tid & 3) * 16;

    const uint32_t smb = smem_u32(sm);
    const uint32_t soff = (uint32_t)(lr * KSTR + lc) * 2;
    const uint32_t offB = (uint32_t)(((lane & 7) + ((lane >> 4) * 8)) * KSTR
                                     + ((lane >> 3) & 1) * 8) * 2;

    auto issue = [&](int kt, int st) {
        const size_t koff = kbase + (size_t)(kt + lr) * DK_ + lc;
        const size_t voff = vbase + (size_t)lr * S_ + kt + lc;
        const uint32_t base = smb + (uint32_t)st * (4 * ASTAGE * 2);
        cpa16(base + soff,                       g_kh + koff);
        cpa16(base + soff + 16,                  g_kh + koff + 8);
        cpa16(base + ASTAGE * 2 + soff,          g_kl + koff);
        cpa16(base + ASTAGE * 2 + soff + 16,     g_kl + koff + 8);
        cpa16(base + 2 * ASTAGE * 2 + soff,      g_vh + voff);
        cpa16(base + 2 * ASTAGE * 2 + soff + 16, g_vh + voff + 8);
        cpa16(base + 3 * ASTAGE * 2 + soff,      g_vl + voff);
        cpa16(base + 3 * ASTAGE * 2 + soff + 16, g_vl + voff + 8);
        cp_commit();
    };

    issue(0, 0);

#pragma unroll
    for (int i = 0; i < S_ / 256; i++)
        smadd[tid + i * 256] = (mask[b * S_ + tid + i * 256] == 0) ? -1e30f : 0.f;

    const size_t qoff = (size_t)bh * S_ * DK_;
    uint32_t aqh[4][4], aql[4][4];
#pragma unroll
    for (int ks = 0; ks < 4; ks++) {
        const int c0 = ks * 16 + 2 * tg;
        const size_t r0 = qoff + (size_t)(qrow0 + g) * DK_;
        const size_t r1 = qoff + (size_t)(qrow0 + g + 8) * DK_;
        aqh[ks][0] = *reinterpret_cast<const uint32_t*>(g_qh + r0 + c0);
        aqh[ks][1] = *reinterpret_cast<const uint32_t*>(g_qh + r1 + c0);
        aqh[ks][2] = *reinterpret_cast<const uint32_t*>(g_qh + r0 + c0 + 8);
        aqh[ks][3] = *reinterpret_cast<const uint32_t*>(g_qh + r1 + c0 + 8);
        aql[ks][0] = *reinterpret_cast<const uint32_t*>(g_ql + r0 + c0);
        aql[ks][1] = *reinterpret_cast<const uint32_t*>(g_ql + r1 + c0);
        aql[ks][2] = *reinterpret_cast<const uint32_t*>(g_ql + r0 + c0 + 8);
        aql[ks][3] = *reinterpret_cast<const uint32_t*>(g_ql + r1 + c0 + 8);
    }

    float accO[8][4];
#pragma unroll
    for (int i = 0; i < 8; i++)
#pragma unroll
        for (int j = 0; j < 4; j++) accO[i][j] = 0.f;

    float sum0 = 0.f, sum1 = 0.f;

    const int NTILES = S_ / 64;
    for (int t = 0; t < NTILES; t++) {
        const int kt = t * 64;
        cp_wait0();
        __syncthreads();
        if (t + 1 < NTILES) issue(kt + 64, (t + 1) & 1);

        const uint32_t bKh = smb + (uint32_t)(t & 1) * (4 * ASTAGE * 2);
        const uint32_t bKl = bKh + ASTAGE * 2;
        const uint32_t bVh = bKh + 2 * ASTAGE * 2;
        const uint32_t bVl = bKh + 3 * ASTAGE * 2;

        float acc[8][4];
#pragma unroll
        for (int i = 0; i < 8; i++)
#pragma unroll
            for (int j = 0; j < 4; j++) acc[i][j] = 0.f;

#pragma unroll
        for (int ks = 0; ks < 4; ks++)
#pragma unroll
            for (int ntp = 0; ntp < 4; ntp++) {
                const uint32_t ro = (uint32_t)(ntp * 16 * KSTR + ks * 16) * 2;
                uint32_t kh4[4], kl4[4];
                ldsm4(kh4, bKh + ro + offB);
                ldsm4(kl4, bKl + ro + offB);
                mma16816(acc[2 * ntp],     aqh[ks], &kh4[0]);
                mma16816(acc[2 * ntp + 1], aqh[ks], &kh4[2]);
                mma16816(acc[2 * ntp],     aqh[ks], &kl4[0]);
                mma16816(acc[2 * ntp + 1], aqh[ks], &kl4[2]);
                mma16816(acc[2 * ntp],     aql[ks], &kh4[0]);
                mma16816(acc[2 * ntp + 1], aql[ks], &kh4[2]);
            }

#pragma unroll
        for (int kb2 = 0; kb2 < 4; kb2++) {
            uint32_t ph[4], pl[4];
#pragma unroll
            for (int half = 0; half < 2; half++) {
                const int nt = 2 * kb2 + half;
                const float ma = smadd[kt + nt * 8 + 2 * tg];
                const float mb = smadd[kt + nt * 8 + 2 * tg + 1];
                const float p0 = fast_exp2(acc[nt][0] + ma);
                const float p1 = fast_exp2(acc[nt][1] + mb);
                const float p2 = fast_exp2(acc[nt][2] + ma);
                const float p3 = fast_exp2(acc[nt][3] + mb);
                sum0 += p0 + p1;
                sum1 += p2 + p3;
                const uint32_t h01 = pack_bf16(p0, p1);
                const uint32_t h23 = pack_bf16(p2, p3);
                const float q0 = p0 - __uint_as_float(h01 << 16);
                const float q1 = p1 - __uint_as_float(h01 & 0xffff0000u);
                const float q2 = p2 - __uint_as_float(h23 << 16);
                const float q3 = p3 - __uint_as_float(h23 & 0xffff0000u);
                ph[2 * half + 0] = h01;
                ph[2 * half + 1] = h23;
                pl[2 * half + 0] = pack_bf16(q0, q1);
                pl[2 * half + 1] = pack_bf16(q2, q3);
            }
#pragma unroll
            for (int ntp = 0; ntp < 4; ntp++) {
                const uint32_t ro = (uint32_t)(ntp * 16 * KSTR + kb2 * 16) * 2;
                uint32_t vh4[4], vl4[4];
                ldsm4(vh4, bVh + ro + offB);
                ldsm4(vl4, bVl + ro + offB);
                mma16816(accO[2 * ntp],     ph, &vh4[0]);
                mma16816(accO[2 * ntp + 1], ph, &vh4[2]);
                mma16816(accO[2 * ntp],     ph, &vl4[0]);
                mma16816(accO[2 * ntp + 1], ph, &vl4[2]);
                mma16816(accO[2 * ntp],     pl, &vh4[0]);
                mma16816(accO[2 * ntp + 1], pl, &vh4[2]);
            }
        }
    }

    sum0 += __shfl_xor_sync(0xffffffffu, sum0, 1);
    sum0 += __shfl_xor_sync(0xffffffffu, sum0, 2);
    sum1 += __shfl_xor_sync(0xffffffffu, sum1, 1);
    sum1 += __shfl_xor_sync(0xffffffffu, sum1, 2);

    // ---- epilogue: normalize, split, write ctx in tile-major layout ----
    const float i0 = 1.f / sum0;
    const float i1 = 1.f / sum1;
    const int m0 = b * S_ + qrow0 + g;
    const int m1 = m0 + 8;
#pragma unroll
    for (int nt2 = 0; nt2 < 8; nt2++) {
        const int col = h * DK_ + nt2 * 8 + 2 * tg;
        float vx0 = accO[nt2][0] * i0, vy0 = accO[nt2][1] * i0;
        float vx1 = accO[nt2][2] * i1, vy1 = accO[nt2][3] * i1;
        __nv_bfloat16 hx, lx, hy, ly;
        const size_t p0 = tm_idx(m0, col, M_);
        split1(vx0, hx, lx); split1(vy0, hy, ly);
        *reinterpret_cast<uint32_t*>(g_Ah[0] + p0) =
            ((uint32_t)__bfloat16_as_ushort(hy) << 16) | __bfloat16_as_ushort(hx);
        *reinterpret_cast<uint32_t*>(g_Al[0] + p0) =
            ((uint32_t)__bfloat16_as_ushort(ly) << 16) | __bfloat16_as_ushort(lx);
        const size_t p1 = tm_idx(m1, col, M_);
        split1(vx1, hx, lx); split1(vy1, hy, ly);
        *reinterpret_cast<uint32_t*>(g_Ah[0] + p1) =
            ((uint32_t)__bfloat16_as_ushort(hy) << 16) | __bfloat16_as_ushort(hx);
        *reinterpret_cast<uint32_t*>(g_Al[0] + p1) =
            ((uint32_t)__bfloat16_as_ushort(ly) << 16) | __bfloat16_as_ushort(lx);
    }
}

// ---------------------------------------------------------------------------
// Launch
// ---------------------------------------------------------------------------
#define ATTN_SMEM (2 * 4 * ASTAGE * 2 + S_ * 4)

extern "C" void kernel_launch(void* const* d_in, const int* in_sizes, int n_in,
                              void* d_out, int out_size)
{
    const float* query = (const float*)d_in[0];
    const float* key   = (const float*)d_in[1];
    const float* value = (const float*)d_in[2];
    const int*   mask  = (const int*)  d_in[3];
    const float* Wq = (const float*)d_in[4];
    const float* bq = (const float*)d_in[5];
    const float* Wk = (const float*)d_in[6];
    const float* bk = (const float*)d_in[7];
    const float* Wv = (const float*)d_in[8];
    const float* bv = (const float*)d_in[9];
    const float* Wo = (const float*)d_in[10];
    const float* bo = (const float*)d_in[11];
    float* out = (float*)d_out;

    cudaFuncSetAttribute(gemm_tc<1>, cudaFuncAttributeMaxDynamicSharedMemorySize, GEMM_SMEM);
    cudaFuncSetAttribute(gemm_tc<0>, cudaFuncAttributeMaxDynamicSharedMemorySize, GEMM_SMEM);
    cudaFuncSetAttribute(attn_tc,    cudaFuncAttributeMaxDynamicSharedMemorySize, ATTN_SMEM);

    dim3 wtg(D_ / 32, D_ / 32, 4);
    split_wt_all<<<wtg, dim3(32, 8)>>>(Wq, Wk, Wv, Wo);
    dim3 sag((M_ * D_ / 4) / 256, 3);
    split_act_all<<<sag, 256>>>(query, key, value);

    dim3 gqkv(D_ / 128, M_ / 256, 3);
    gemm_tc<1><<<gqkv, 512, GEMM_SMEM>>>(bq, bk, bv, nullptr);

    dim3 agrid(S_ / 128, B_ * H_);
    attn_tc<<<agrid, 256, ATTN_SMEM>>>(mask);

    dim3 gout(D_ / 128, M_ / 256);
    gemm_tc<0><<<gout, 512, GEMM_SMEM>>>(bo, nullptr, nullptr, out);
}

// round 15
// speedup vs baseline: 1.2704x; 1.0974x over previous
#include <cuda_runtime.h>
#include <cuda_bf16.h>
#include <stdint.h>

// Problem constants
#define B_  2
#define S_  2048
#define D_  1024
#define H_  16
#define DK_ 64
#define M_  (B_ * S_)

#define QSCALE (0.125f * 1.44269504088896340736f)

// ---------------------------------------------------------------------------
// Scratch (device globals — no allocations allowed)
// Tile-major swizzled layouts (k-chunk outer, 32-k inner with XOR sub-chunk):
//   elem (row, k) -> ((k>>5)*NROWS + row)*32 + (((k&31)>>3) ^ ((row>>1)&3))*8 + (k&7)
// A/W: row = matrix row, k = reduction dim.  K: row = s, k = dk (per bh).
// V:  row = dk, k = s (per bh).  Contiguous per (chunk, row-range) -> bulk-copyable.
// ---------------------------------------------------------------------------
__device__ __nv_bfloat16 g_Ah[3][M_ * D_];
__device__ __nv_bfloat16 g_Al[3][M_ * D_];
__device__ __nv_bfloat16 g_Wh[4][D_ * D_];
__device__ __nv_bfloat16 g_Wl[4][D_ * D_];

__device__ __nv_bfloat16 g_qh[B_ * H_ * S_ * DK_];  // [bh][s][dk] row-major, pre-scaled
__device__ __nv_bfloat16 g_ql[B_ * H_ * S_ * DK_];
__device__ __nv_bfloat16 g_kh[B_ * H_ * S_ * DK_];  // tile-major per bh (row=s,k=dk)
__device__ __nv_bfloat16 g_kl[B_ * H_ * S_ * DK_];
__device__ __nv_bfloat16 g_vh[B_ * H_ * DK_ * S_];  // tile-major per bh (row=dk,k=s)
__device__ __nv_bfloat16 g_vl[B_ * H_ * DK_ * S_];

// ---------------------------------------------------------------------------
// Helpers
// ---------------------------------------------------------------------------
__device__ __forceinline__ size_t tm_idx(int row, int k, int nrows) {
    const int chunk = k >> 5;
    const int cc = k & 31;
    const int sc = (cc >> 3) ^ ((row >> 1) & 3);
    return ((size_t)chunk * nrows + row) * 32 + sc * 8 + (cc & 7);
}

__device__ __forceinline__ void split1(float x, __nv_bfloat16& h, __nv_bfloat16& l) {
    h = __float2bfloat16_rn(x);
    l = __float2bfloat16_rn(x - __bfloat162float(h));
}

__device__ __forceinline__ uint32_t pack_bf16(float lo, float hi) {
    uint32_t r;
    asm("cvt.rn.bf16x2.f32 %0, %1, %2;" : "=r"(r) : "f"(hi), "f"(lo));
    return r;
}

__device__ __forceinline__ float fast_exp2(float x) {
    float r;
    asm("ex2.approx.f32 %0, %1;" : "=f"(r) : "f"(x));
    return r;
}

__device__ __forceinline__ void mma16816(float* c, const uint32_t* a, const uint32_t* b)
{
    asm("mma.sync.aligned.m16n8k16.row.col.f32.bf16.bf16.f32 "
        "{%0,%1,%2,%3},{%4,%5,%6,%7},{%8,%9},{%0,%1,%2,%3};"
        : "+f"(c[0]), "+f"(c[1]), "+f"(c[2]), "+f"(c[3])
        : "r"(a[0]), "r"(a[1]), "r"(a[2]), "r"(a[3]), "r"(b[0]), "r"(b[1]));
}

__device__ __forceinline__ void ldsm4(uint32_t* r, uint32_t addr)
{
    asm volatile("ldmatrix.sync.aligned.m8n8.x4.shared.b16 {%0,%1,%2,%3}, [%4];"
        : "=r"(r[0]), "=r"(r[1]), "=r"(r[2]), "=r"(r[3]) : "r"(addr));
}

__device__ __forceinline__ uint32_t smem_u32(const void* p) {
    return (uint32_t)__cvta_generic_to_shared(p);
}

__device__ __forceinline__ void bulk_g2s(uint32_t dst, const void* src,
                                         uint32_t bytes, uint32_t mbar)
{
    asm volatile("cp.async.bulk.shared::cta.global.mbarrier::complete_tx::bytes "
                 "[%0], [%1], %2, [%3];"
        :: "r"(dst), "l"(src), "r"(bytes), "r"(mbar) : "memory");
}

#define MBAR_INIT(mbar, count) \
    asm volatile("mbarrier.init.shared.b64 [%0], %1;" \
        :: "r"((uint32_t)(mbar)), "r"((uint32_t)(count)) : "memory")
#define MBAR_EXPECT_TX(mbar, tx) \
    asm volatile("mbarrier.arrive.expect_tx.shared.b64 _, [%0], %1;" \
        :: "r"((uint32_t)(mbar)), "r"((uint32_t)(tx)) : "memory")
#define MBAR_WAIT(mbar, parity) do { \
    uint32_t _m = (uint32_t)(mbar); uint32_t _p = (uint32_t)(parity); uint32_t _d; \
    asm volatile("{\n\t.reg .pred p;\n\t" \
        "mbarrier.try_wait.parity.acquire.cta.shared::cta.b64 p, [%1], %2;\n\t" \
        "selp.b32 %0, 1, 0, p;\n\t}" : "=r"(_d) : "r"(_m), "r"(_p) : "memory"); \
    if (!_d) { \
        asm volatile("{\n\t.reg .pred P1;\n\t" \
            "WL_%=:\n\t" \
            "mbarrier.try_wait.parity.acquire.cta.shared::cta.b64 P1, [%0], %1, 0x989680;\n\t" \
            "@P1 bra.uni WD_%=;\n\tbra.uni WL_%=;\n\tWD_%=:\n\t}" \
            :: "r"(_m), "r"(_p) : "memory"); \
    } \
} while (0)

// ---------------------------------------------------------------------------
// Split kernels — tile-major swizzled layout (unchanged from R14).
// ---------------------------------------------------------------------------
__global__ __launch_bounds__(256)
void split_act_all(const float* __restrict__ q, const float* __restrict__ k,
                   const float* __restrict__ v)
{
    const int z = blockIdx.y;
    const float* src = (z == 0) ? q : (z == 1) ? k : v;
    const int i = blockIdx.x * 256 + threadIdx.x;
    const int m  = i >> 8;
    const int k0 = (i & 255) * 4;
    float4 val = reinterpret_cast<const float4*>(src)[i];
    __nv_bfloat16 h0, h1, h2, h3, l0, l1, l2, l3;
    split1(val.x, h0, l0); split1(val.y, h1, l1);
    split1(val.z, h2, l2); split1(val.w, h3, l3);
    uint2 hp, lp;
    hp.x = ((uint32_t)__bfloat16_as_ushort(h1) << 16) | __bfloat16_as_ushort(h0);
    hp.y = ((uint32_t)__bfloat16_as_ushort(h3) << 16) | __bfloat16_as_ushort(h2);
    lp.x = ((uint32_t)__bfloat16_as_ushort(l1) << 16) | __bfloat16_as_ushort(l0);
    lp.y = ((uint32_t)__bfloat16_as_ushort(l3) << 16) | __bfloat16_as_ushort(l2);
    const size_t pos = tm_idx(m, k0, M_);
    *reinterpret_cast<uint2*>(g_Ah[z] + pos) = hp;
    *reinterpret_cast<uint2*>(g_Al[z] + pos) = lp;
}

__global__ __launch_bounds__(256)
void split_wt_all(const float* __restrict__ Wq, const float* __restrict__ Wk,
                  const float* __restrict__ Wv, const float* __restrict__ Wo)
{
    __shared__ float tile[32][33];
    const int z = blockIdx.z;
    const float* W = (z == 0) ? Wq : (z == 1) ? Wk : (z == 2) ? Wv : Wo;
    const int tx = threadIdx.x;
    const int ty = threadIdx.y;
    const int n0 = blockIdx.x * 32;
    const int k0 = blockIdx.y * 32;
#pragma unroll
    for (int i = 0; i < 32; i += 8)
        tile[ty + i][tx] = W[(size_t)(k0 + ty + i) * D_ + n0 + tx];
    __syncthreads();
#pragma unroll
    for (int i = 0; i < 32; i += 8) {
        float v = tile[tx][ty + i];
        __nv_bfloat16 h, l;
        split1(v, h, l);
        const size_t idx = tm_idx(n0 + ty + i, k0 + tx, D_);
        g_Wh[z][idx] = h;
        g_Wl[z][idx] = l;
    }
}

// ---------------------------------------------------------------------------
// Tensor-core GEMM (bf16x3): 256x128 tile, 512 threads, cp.async.bulk — R14,
// with K/V epilogues writing the new tile-major K/V layouts.
// ---------------------------------------------------------------------------
#define STB 49152
#define GEMM_SMEM (128 + 2 * STB)

template <int MODE>
__global__ __launch_bounds__(512)
void gemm_tc(const float* __restrict__ bias0, const float* __restrict__ bias1,
             const float* __restrict__ bias2, float* __restrict__ Cout)
{
    extern __shared__ char smc[];

    const int z = (MODE == 1) ? blockIdx.z : 0;
    const __nv_bfloat16* Ah = g_Ah[z];
    const __nv_bfloat16* Al = g_Al[z];
    const __nv_bfloat16* Wh = g_Wh[(MODE == 0) ? 3 : z];
    const __nv_bfloat16* Wl = g_Wl[(MODE == 0) ? 3 : z];
    const float* bias = (MODE == 0) ? bias0 : (z == 0) ? bias0 : (z == 1) ? bias1 : bias2;
    const float oscale = (MODE == 1 && z == 0) ? QSCALE : 1.0f;

    const int tid = threadIdx.x;
    const int bm = blockIdx.y * 256;
    const int bn = blockIdx.x * 128;

    const int lane = tid & 31;
    const int wid  = tid >> 5;
    const int wm   = wid & 7;
    const int wn   = wid >> 3;
    const int g    = lane >> 2;
    const int tg   = lane & 3;

    const uint32_t smb = smem_u32(smc);
    const uint32_t mb0 = smb, mb1 = smb + 8;

    if (tid == 0) {
        MBAR_INIT(mb0, 1);
        MBAR_INIT(mb1, 1);
    }
    __syncthreads();

    const int rrA = (lane & 7) + ((lane >> 3) & 1) * 8;
    const int khA = lane >> 4;
    const int rrB = (lane & 7) + (lane >> 4) * 8;
    const int khB = (lane >> 3) & 1;

    auto issue = [&](int t) {
        const uint32_t mb = (t & 1) ? mb1 : mb0;
        const uint32_t base = smb + 128 + (uint32_t)(t & 1) * STB;
        MBAR_EXPECT_TX(mb, STB);
        bulk_g2s(base,         Ah + ((size_t)t * M_ + bm) * 32, 16384, mb);
        bulk_g2s(base + 16384, Al + ((size_t)t * M_ + bm) * 32, 16384, mb);
        bulk_g2s(base + 32768, Wh + ((size_t)t * D_ + bn) * 32, 8192,  mb);
        bulk_g2s(base + 40960, Wl + ((size_t)t * D_ + bn) * 32, 8192,  mb);
    };

    float acc[2][8][4];
#pragma unroll
    for (int mt = 0; mt < 2; mt++)
#pragma unroll
        for (int nt = 0; nt < 8; nt++)
#pragma unroll
            for (int i = 0; i < 4; i++) acc[mt][nt][i] = 0.f;

    if (tid == 0) issue(0);

    const int NT = D_ / 32;
    for (int t = 0; t < NT; t++) {
        if (t + 1 < NT) {
            __syncthreads();
            if (tid == 0) issue(t + 1);
        }
        MBAR_WAIT((t & 1) ? mb1 : mb0, (t >> 1) & 1);

        const uint32_t base = smb + 128 + (uint32_t)(t & 1) * STB;
        const uint32_t bAh = base;
        const uint32_t bAl = base + 16384;
        const uint32_t bBh = base + 32768;
        const uint32_t bBl = base + 40960;

#pragma unroll
        for (int kk = 0; kk < 32; kk += 16) {
            uint32_t ah[2][4], al[2][4];
#pragma unroll
            for (int mt = 0; mt < 2; mt++) {
                const int row = wm * 32 + mt * 16 + rrA;
                const int sc = ((kk >> 3) + khA) ^ ((row >> 1) & 3);
                const uint32_t off = (uint32_t)(row * 64 + sc * 16);
                ldsm4(ah[mt], bAh + off);
                ldsm4(al[mt], bAl + off);
            }
#pragma unroll
            for (int ntp = 0; ntp < 4; ntp++) {
                const int row = wn * 64 + ntp * 16 + rrB;
                const int sc = ((kk >> 3) + khB) ^ ((row >> 1) & 3);
                const uint32_t off = (uint32_t)(row * 64 + sc * 16);
                uint32_t bh4[4], bl4[4];
                ldsm4(bh4, bBh + off);
                ldsm4(bl4, bBl + off);
                mma16816(acc[0][2 * ntp],     ah[0], &bh4[0]);
                mma16816(acc[1][2 * ntp],     ah[1], &bh4[0]);
                mma16816(acc[0][2 * ntp + 1], ah[0], &bh4[2]);
                mma16816(acc[1][2 * ntp + 1], ah[1], &bh4[2]);
                mma16816(acc[0][2 * ntp],     ah[0], &bl4[0]);
                mma16816(acc[1][2 * ntp],     ah[1], &bl4[0]);
                mma16816(acc[0][2 * ntp + 1], ah[0], &bl4[2]);
                mma16816(acc[1][2 * ntp + 1], ah[1], &bl4[2]);
                mma16816(acc[0][2 * ntp],     al[0], &bh4[0]);
                mma16816(acc[1][2 * ntp],     al[1], &bh4[0]);
                mma16816(acc[0][2 * ntp + 1], al[0], &bh4[2]);
                mma16816(acc[1][2 * ntp + 1], al[1], &bh4[2]);
            }
        }
    }

    // Epilogue
#pragma unroll
    for (int mt = 0; mt < 2; mt++) {
#pragma unroll
        for (int nt = 0; nt < 8; nt++) {
            const int col = bn + wn * 64 + nt * 8 + tg * 2;
            const float b0 = bias[col], b1 = bias[col + 1];
#pragma unroll
            for (int half = 0; half < 2; half++) {
                const int row = bm + wm * 32 + mt * 16 + g + half * 8;
                float vx = acc[mt][nt][half * 2 + 0] + b0;
                float vy = acc[mt][nt][half * 2 + 1] + b1;
                if (MODE == 0) {
                    *reinterpret_cast<float2*>(Cout + (size_t)row * D_ + col) =
                        make_float2(vx, vy);
                } else {
                    vx *= oscale; vy *= oscale;
                    __nv_bfloat16 hx, lx, hy, ly;
                    split1(vx, hx, lx);
                    split1(vy, hy, ly);
                    const int b  = row >> 11;
                    const int s  = row & (S_ - 1);
                    const int h  = col >> 6;
                    const int dk = col & (DK_ - 1);
                    const size_t bh = (size_t)b * H_ + h;
                    if (z == 0) {
                        const size_t idx = (bh * S_ + s) * DK_ + dk;
                        *reinterpret_cast<uint32_t*>(g_qh + idx) =
                            ((uint32_t)__bfloat16_as_ushort(hy) << 16) | __bfloat16_as_ushort(hx);
                        *reinterpret_cast<uint32_t*>(g_ql + idx) =
                            ((uint32_t)__bfloat16_as_ushort(ly) << 16) | __bfloat16_as_ushort(lx);
                    } else if (z == 1) {
                        // K tile-major per bh: row=s, k=dk, nrows=S_
                        const size_t idx = bh * S_ * DK_ + tm_idx(s, dk, S_);
                        *reinterpret_cast<uint32_t*>(g_kh + idx) =
                            ((uint32_t)__bfloat16_as_ushort(hy) << 16) | __bfloat16_as_ushort(hx);
                        *reinterpret_cast<uint32_t*>(g_kl + idx) =
                            ((uint32_t)__bfloat16_as_ushort(ly) << 16) | __bfloat16_as_ushort(lx);
                    } else {
                        // V tile-major per bh: row=dk, k=s, nrows=DK_
                        const size_t i0 = bh * DK_ * S_ + tm_idx(dk,     s, DK_);
                        const size_t i1 = bh * DK_ * S_ + tm_idx(dk + 1, s, DK_);
                        g_vh[i0] = hx;
                        g_vh[i1] = hy;
                        g_vl[i0] = lx;
                        g_vl[i1] = ly;
                    }
                }
            }
        }
    }
}

// ---------------------------------------------------------------------------
// Tensor-core flash attention (bf16x3): R12 math, cp.async.bulk K/V loads
// (8 bulk ops / tile instead of 2048 LDGSTS), stride-64 swizzled smem tiles.
// smem: [mb0|mb1 (128B)] [stage0 32KB: Kh|Kl|Vh|Vl] [stage1 32KB] [mask 8KB]
// ---------------------------------------------------------------------------
#define ATB 32768
#define ATTN_SMEM (128 + 2 * ATB + S_ * 4)

__global__ __launch_bounds__(256, 2)
void attn_tc(const int* __restrict__ mask)
{
    extern __shared__ char smc[];
    float* smadd = reinterpret_cast<float*>(smc + 128 + 2 * ATB);

    const int bh = blockIdx.y;
    const int b  = bh >> 4;
    const int h  = bh & 15;
    const int tid  = threadIdx.x;
    const int lane = tid & 31;
    const int wid  = tid >> 5;
    const int g    = lane >> 2;
    const int tg   = lane & 3;
    const int qrow0 = blockIdx.x * 128 + wid * 16;

    const size_t kbh = (size_t)bh * S_ * DK_;
    const size_t vbh = (size_t)bh * DK_ * S_;

    const uint32_t smb = smem_u32(smc);
    const uint32_t mb0 = smb, mb1 = smb + 8;

    if (tid == 0) {
        MBAR_INIT(mb0, 1);
        MBAR_INIT(mb1, 1);
    }
    __syncthreads();

    const int rrB = (lane & 7) + (lane >> 4) * 8;
    const int khB = (lane >> 3) & 1;

    auto issue = [&](int t) {
        const uint32_t mb = (t & 1) ? mb1 : mb0;
        const uint32_t base = smb + 128 + (uint32_t)(t & 1) * ATB;
        const int kt = t * 64;
        MBAR_EXPECT_TX(mb, ATB);
        // K: dk-chunks 0,1; rows kt..kt+63 contiguous per chunk
        bulk_g2s(base,          g_kh + kbh + (size_t)(0 * S_ + kt) * 32, 4096, mb);
        bulk_g2s(base + 4096,   g_kh + kbh + (size_t)(1 * S_ + kt) * 32, 4096, mb);
        bulk_g2s(base + 8192,   g_kl + kbh + (size_t)(0 * S_ + kt) * 32, 4096, mb);
        bulk_g2s(base + 12288,  g_kl + kbh + (size_t)(1 * S_ + kt) * 32, 4096, mb);
        // V: s-chunks 2t, 2t+1; all 64 dk rows contiguous per chunk
        bulk_g2s(base + 16384,  g_vh + vbh + (size_t)(2 * t + 0) * DK_ * 32, 4096, mb);
        bulk_g2s(base + 20480,  g_vh + vbh + (size_t)(2 * t + 1) * DK_ * 32, 4096, mb);
        bulk_g2s(base + 24576,  g_vl + vbh + (size_t)(2 * t + 0) * DK_ * 32, 4096, mb);
        bulk_g2s(base + 28672,  g_vl + vbh + (size_t)(2 * t + 1) * DK_ * 32, 4096, mb);
    };

    if (tid == 0) issue(0);

#pragma unroll
    for (int i = 0; i < S_ / 256; i++)
        smadd[tid + i * 256] = (mask[b * S_ + tid + i * 256] == 0) ? -1e30f : 0.f;

    const size_t qoff = (size_t)bh * S_ * DK_;
    uint32_t aqh[4][4], aql[4][4];
#pragma unroll
    for (int ks = 0; ks < 4; ks++) {
        const int c0 = ks * 16 + 2 * tg;
        const size_t r0 = qoff + (size_t)(qrow0 + g) * DK_;
        const size_t r1 = qoff + (size_t)(qrow0 + g + 8) * DK_;
        aqh[ks][0] = *reinterpret_cast<const uint32_t*>(g_qh + r0 + c0);
        aqh[ks][1] = *reinterpret_cast<const uint32_t*>(g_qh + r1 + c0);
        aqh[ks][2] = *reinterpret_cast<const uint32_t*>(g_qh + r0 + c0 + 8);
        aqh[ks][3] = *reinterpret_cast<const uint32_t*>(g_qh + r1 + c0 + 8);
        aql[ks][0] = *reinterpret_cast<const uint32_t*>(g_ql + r0 + c0);
        aql[ks][1] = *reinterpret_cast<const uint32_t*>(g_ql + r1 + c0);
        aql[ks][2] = *reinterpret_cast<const uint32_t*>(g_ql + r0 + c0 + 8);
        aql[ks][3] = *reinterpret_cast<const uint32_t*>(g_ql + r1 + c0 + 8);
    }

    float accO[8][4];
#pragma unroll
    for (int i = 0; i < 8; i++)
#pragma unroll
        for (int j = 0; j < 4; j++) accO[i][j] = 0.f;

    float sum0 = 0.f, sum1 = 0.f;

    const int NTILES = S_ / 64;
    for (int t = 0; t < NTILES; t++) {
        const int kt = t * 64;
        if (t + 1 < NTILES) {
            __syncthreads();           // stage (t+1)&1 free (compute t-1 done)
            if (tid == 0) issue(t + 1);
        }
        MBAR_WAIT((t & 1) ? mb1 : mb0, (t >> 1) & 1);

        const uint32_t base = smb + 128 + (uint32_t)(t & 1) * ATB;
        const uint32_t bKh = base;
        const uint32_t bKl = base + 8192;
        const uint32_t bVh = base + 16384;
        const uint32_t bVl = base + 24576;

        // ---- S = Q K^T ----
        float acc[8][4];
#pragma unroll
        for (int i = 0; i < 8; i++)
#pragma unroll
            for (int j = 0; j < 4; j++) acc[i][j] = 0.f;

#pragma unroll
        for (int ks = 0; ks < 4; ks++)
#pragma unroll
            for (int ntp = 0; ntp < 4; ntp++) {
                const int row = ntp * 16 + rrB;            // key row within tile
                const int kdk = ks * 16 + khB * 8;          // dk
                const int sc = ((kdk >> 3) & 3) ^ ((row >> 1) & 3);
                const uint32_t off = (uint32_t)((kdk >> 5) * 4096 + row * 64 + sc * 16);
                uint32_t kh4[4], kl4[4];
                ldsm4(kh4, bKh + off);
                ldsm4(kl4, bKl + off);
                mma16816(acc[2 * ntp],     aqh[ks], &kh4[0]);
                mma16816(acc[2 * ntp + 1], aqh[ks], &kh4[2]);
                mma16816(acc[2 * ntp],     aqh[ks], &kl4[0]);
                mma16816(acc[2 * ntp + 1], aqh[ks], &kl4[2]);
                mma16816(acc[2 * ntp],     aql[ks], &kh4[0]);
                mma16816(acc[2 * ntp + 1], aql[ks], &kh4[2]);
            }

        // ---- fused per-group softmax + PV ----
#pragma unroll
        for (int kb2 = 0; kb2 < 4; kb2++) {
            uint32_t ph[4], pl[4];
#pragma unroll
            for (int half = 0; half < 2; half++) {
                const int nt = 2 * kb2 + half;
                const float ma = smadd[kt + nt * 8 + 2 * tg];
                const float mb = smadd[kt + nt * 8 + 2 * tg + 1];
                const float p0 = fast_exp2(acc[nt][0] + ma);
                const float p1 = fast_exp2(acc[nt][1] + mb);
                const float p2 = fast_exp2(acc[nt][2] + ma);
                const float p3 = fast_exp2(acc[nt][3] + mb);
                sum0 += p0 + p1;
                sum1 += p2 + p3;
                const uint32_t h01 = pack_bf16(p0, p1);
                const uint32_t h23 = pack_bf16(p2, p3);
                const float q0 = p0 - __uint_as_float(h01 << 16);
                const float q1 = p1 - __uint_as_float(h01 & 0xffff0000u);
                const float q2 = p2 - __uint_as_float(h23 << 16);
                const float q3 = p3 - __uint_as_float(h23 & 0xffff0000u);
                ph[2 * half + 0] = h01;
                ph[2 * half + 1] = h23;
                pl[2 * half + 0] = pack_bf16(q0, q1);
                pl[2 * half + 1] = pack_bf16(q2, q3);
            }
#pragma unroll
            for (int ntp = 0; ntp < 4; ntp++) {
                const int row = ntp * 16 + rrB;             // dk row
                const int kss = kb2 * 16 + khB * 8;         // s within tile
                const int sc = ((kss >> 3) & 3) ^ ((row >> 1) & 3);
                const uint32_t off = (uint32_t)((kss >> 5) * 4096 + row * 64 + sc * 16);
                uint32_t vh4[4], vl4[4];
                ldsm4(vh4, bVh + off);
                ldsm4(vl4, bVl + off);
                mma16816(accO[2 * ntp],     ph, &vh4[0]);
                mma16816(accO[2 * ntp + 1], ph, &vh4[2]);
                mma16816(accO[2 * ntp],     ph, &vl4[0]);
                mma16816(accO[2 * ntp + 1], ph, &vl4[2]);
                mma16816(accO[2 * ntp],     pl, &vh4[0]);
                mma16816(accO[2 * ntp + 1], pl, &vh4[2]);
            }
        }
    }

    sum0 += __shfl_xor_sync(0xffffffffu, sum0, 1);
    sum0 += __shfl_xor_sync(0xffffffffu, sum0, 2);
    sum1 += __shfl_xor_sync(0xffffffffu, sum1, 1);
    sum1 += __shfl_xor_sync(0xffffffffu, sum1, 2);

    // ---- epilogue: normalize, split, write ctx in tile-major layout ----
    const float i0 = 1.f / sum0;
    const float i1 = 1.f / sum1;
    const int m0 = b * S_ + qrow0 + g;
    const int m1 = m0 + 8;
#pragma unroll
    for (int nt2 = 0; nt2 < 8; nt2++) {
        const int col = h * DK_ + nt2 * 8 + 2 * tg;
        float vx0 = accO[nt2][0] * i0, vy0 = accO[nt2][1] * i0;
        float vx1 = accO[nt2][2] * i1, vy1 = accO[nt2][3] * i1;
        __nv_bfloat16 hx, lx, hy, ly;
        const size_t p0 = tm_idx(m0, col, M_);
        split1(vx0, hx, lx); split1(vy0, hy, ly);
        *reinterpret_cast<uint32_t*>(g_Ah[0] + p0) =
            ((uint32_t)__bfloat16_as_ushort(hy) << 16) | __bfloat16_as_ushort(hx);
        *reinterpret_cast<uint32_t*>(g_Al[0] + p0) =
            ((uint32_t)__bfloat16_as_ushort(ly) << 16) | __bfloat16_as_ushort(lx);
        const size_t p1 = tm_idx(m1, col, M_);
        split1(vx1, hx, lx); split1(vy1, hy, ly);
        *reinterpret_cast<uint32_t*>(g_Ah[0] + p1) =
            ((uint32_t)__bfloat16_as_ushort(hy) << 16) | __bfloat16_as_ushort(hx);
        *reinterpret_cast<uint32_t*>(g_Al[0] + p1) =
            ((uint32_t)__bfloat16_as_ushort(ly) << 16) | __bfloat16_as_ushort(lx);
    }
}

// ---------------------------------------------------------------------------
// Launch
// ---------------------------------------------------------------------------
extern "C" void kernel_launch(void* const* d_in, const int* in_sizes, int n_in,
                              void* d_out, int out_size)
{
    const float* query = (const float*)d_in[0];
    const float* key   = (const float*)d_in[1];
    const float* value = (const float*)d_in[2];
    const int*   mask  = (const int*)  d_in[3];
    const float* Wq = (const float*)d_in[4];
    const float* bq = (const float*)d_in[5];
    const float* Wk = (const float*)d_in[6];
    const float* bk = (const float*)d_in[7];
    const float* Wv = (const float*)d_in[8];
    const float* bv = (const float*)d_in[9];
    const float* Wo = (const float*)d_in[10];
    const float* bo = (const float*)d_in[11];
    float* out = (float*)d_out;

    cudaFuncSetAttribute(gemm_tc<1>, cudaFuncAttributeMaxDynamicSharedMemorySize, GEMM_SMEM);
    cudaFuncSetAttribute(gemm_tc<0>, cudaFuncAttributeMaxDynamicSharedMemorySize, GEMM_SMEM);
    cudaFuncSetAttribute(attn_tc,    cudaFuncAttributeMaxDynamicSharedMemorySize, ATTN_SMEM);

    dim3 wtg(D_ / 32, D_ / 32, 4);
    split_wt_all<<<wtg, dim3(32, 8)>>>(Wq, Wk, Wv, Wo);
    dim3 sag((M_ * D_ / 4) / 256, 3);
    split_act_all<<<sag, 256>>>(query, key, value);

    dim3 gqkv(D_ / 128, M_ / 256, 3);
    gemm_tc<1><<<gqkv, 512, GEMM_SMEM>>>(bq, bk, bv, nullptr);

    dim3 agrid(S_ / 128, B_ * H_);
    attn_tc<<<agrid, 256, ATTN_SMEM>>>(mask);

    dim3 gout(D_ / 128, M_ / 256);
    gemm_tc<0><<<gout, 512, GEMM_SMEM>>>(bo, nullptr, nullptr, out);
}

// round 16
// speedup vs baseline: 1.3009x; 1.0240x over previous
#include <cuda_runtime.h>
#include <cuda_bf16.h>
#include <stdint.h>

// Problem constants
#define B_  2
#define S_  2048
#define D_  1024
#define H_  16
#define DK_ 64
#define M_  (B_ * S_)

#define QSCALE (0.125f * 1.44269504088896340736f)

// ---------------------------------------------------------------------------
// Scratch (device globals — no allocations allowed)
// Tile-major swizzled layouts (k-chunk outer, 32-k inner with XOR sub-chunk):
//   elem (row, k) -> ((k>>5)*NROWS + row)*32 + (((k&31)>>3) ^ ((row>>1)&3))*8 + (k&7)
// ---------------------------------------------------------------------------
__device__ __nv_bfloat16 g_Ah[3][M_ * D_];
__device__ __nv_bfloat16 g_Al[3][M_ * D_];
__device__ __nv_bfloat16 g_Wh[4][D_ * D_];
__device__ __nv_bfloat16 g_Wl[4][D_ * D_];

__device__ __nv_bfloat16 g_qh[B_ * H_ * S_ * DK_];  // [bh][s][dk] row-major, pre-scaled
__device__ __nv_bfloat16 g_ql[B_ * H_ * S_ * DK_];
__device__ __nv_bfloat16 g_kh[B_ * H_ * S_ * DK_];  // tile-major per bh (row=s,k=dk)
__device__ __nv_bfloat16 g_kl[B_ * H_ * S_ * DK_];
__device__ __nv_bfloat16 g_vh[B_ * H_ * DK_ * S_];  // tile-major per bh (row=dk,k=s)
__device__ __nv_bfloat16 g_vl[B_ * H_ * DK_ * S_];

// ---------------------------------------------------------------------------
// Helpers
// ---------------------------------------------------------------------------
__device__ __forceinline__ size_t tm_idx(int row, int k, int nrows) {
    const int chunk = k >> 5;
    const int cc = k & 31;
    const int sc = (cc >> 3) ^ ((row >> 1) & 3);
    return ((size_t)chunk * nrows + row) * 32 + sc * 8 + (cc & 7);
}

__device__ __forceinline__ void split1(float x, __nv_bfloat16& h, __nv_bfloat16& l) {
    h = __float2bfloat16_rn(x);
    l = __float2bfloat16_rn(x - __bfloat162float(h));
}

__device__ __forceinline__ uint32_t pack_bf16(float lo, float hi) {
    uint32_t r;
    asm("cvt.rn.bf16x2.f32 %0, %1, %2;" : "=r"(r) : "f"(hi), "f"(lo));
    return r;
}

__device__ __forceinline__ float fast_exp2(float x) {
    float r;
    asm("ex2.approx.f32 %0, %1;" : "=f"(r) : "f"(x));
    return r;
}

__device__ __forceinline__ void mma16816(float* c, const uint32_t* a, const uint32_t* b)
{
    asm("mma.sync.aligned.m16n8k16.row.col.f32.bf16.bf16.f32 "
        "{%0,%1,%2,%3},{%4,%5,%6,%7},{%8,%9},{%0,%1,%2,%3};"
        : "+f"(c[0]), "+f"(c[1]), "+f"(c[2]), "+f"(c[3])
        : "r"(a[0]), "r"(a[1]), "r"(a[2]), "r"(a[3]), "r"(b[0]), "r"(b[1]));
}

__device__ __forceinline__ void ldsm4(uint32_t* r, uint32_t addr)
{
    asm volatile("ldmatrix.sync.aligned.m8n8.x4.shared.b16 {%0,%1,%2,%3}, [%4];"
        : "=r"(r[0]), "=r"(r[1]), "=r"(r[2]), "=r"(r[3]) : "r"(addr));
}

__device__ __forceinline__ uint32_t smem_u32(const void* p) {
    return (uint32_t)__cvta_generic_to_shared(p);
}

__device__ __forceinline__ void bulk_g2s(uint32_t dst, const void* src,
                                         uint32_t bytes, uint32_t mbar)
{
    asm volatile("cp.async.bulk.shared::cta.global.mbarrier::complete_tx::bytes "
                 "[%0], [%1], %2, [%3];"
        :: "r"(dst), "l"(src), "r"(bytes), "r"(mbar) : "memory");
}

#define MBAR_INIT(mbar, count) \
    asm volatile("mbarrier.init.shared.b64 [%0], %1;" \
        :: "r"((uint32_t)(mbar)), "r"((uint32_t)(count)) : "memory")
#define MBAR_EXPECT_TX(mbar, tx) \
    asm volatile("mbarrier.arrive.expect_tx.shared.b64 _, [%0], %1;" \
        :: "r"((uint32_t)(mbar)), "r"((uint32_t)(tx)) : "memory")
#define MBAR_WAIT(mbar, parity) do { \
    uint32_t _m = (uint32_t)(mbar); uint32_t _p = (uint32_t)(parity); uint32_t _d; \
    asm volatile("{\n\t.reg .pred p;\n\t" \
        "mbarrier.try_wait.parity.acquire.cta.shared::cta.b64 p, [%1], %2;\n\t" \
        "selp.b32 %0, 1, 0, p;\n\t}" : "=r"(_d) : "r"(_m), "r"(_p) : "memory"); \
    if (!_d) { \
        asm volatile("{\n\t.reg .pred P1;\n\t" \
            "WL_%=:\n\t" \
            "mbarrier.try_wait.parity.acquire.cta.shared::cta.b64 P1, [%0], %1, 0x989680;\n\t" \
            "@P1 bra.uni WD_%=;\n\tbra.uni WL_%=;\n\tWD_%=:\n\t}" \
            :: "r"(_m), "r"(_p) : "memory"); \
    } \
} while (0)

// ---------------------------------------------------------------------------
// Split kernels — tile-major swizzled layout (unchanged).
// ---------------------------------------------------------------------------
__global__ __launch_bounds__(256)
void split_act_all(const float* __restrict__ q, const float* __restrict__ k,
                   const float* __restrict__ v)
{
    const int z = blockIdx.y;
    const float* src = (z == 0) ? q : (z == 1) ? k : v;
    const int i = blockIdx.x * 256 + threadIdx.x;
    const int m  = i >> 8;
    const int k0 = (i & 255) * 4;
    float4 val = reinterpret_cast<const float4*>(src)[i];
    __nv_bfloat16 h0, h1, h2, h3, l0, l1, l2, l3;
    split1(val.x, h0, l0); split1(val.y, h1, l1);
    split1(val.z, h2, l2); split1(val.w, h3, l3);
    uint2 hp, lp;
    hp.x = ((uint32_t)__bfloat16_as_ushort(h1) << 16) | __bfloat16_as_ushort(h0);
    hp.y = ((uint32_t)__bfloat16_as_ushort(h3) << 16) | __bfloat16_as_ushort(h2);
    lp.x = ((uint32_t)__bfloat16_as_ushort(l1) << 16) | __bfloat16_as_ushort(l0);
    lp.y = ((uint32_t)__bfloat16_as_ushort(l3) << 16) | __bfloat16_as_ushort(l2);
    const size_t pos = tm_idx(m, k0, M_);
    *reinterpret_cast<uint2*>(g_Ah[z] + pos) = hp;
    *reinterpret_cast<uint2*>(g_Al[z] + pos) = lp;
}

__global__ __launch_bounds__(256)
void split_wt_all(const float* __restrict__ Wq, const float* __restrict__ Wk,
                  const float* __restrict__ Wv, const float* __restrict__ Wo)
{
    __shared__ float tile[32][33];
    const int z = blockIdx.z;
    const float* W = (z == 0) ? Wq : (z == 1) ? Wk : (z == 2) ? Wv : Wo;
    const int tx = threadIdx.x;
    const int ty = threadIdx.y;
    const int n0 = blockIdx.x * 32;
    const int k0 = blockIdx.y * 32;
#pragma unroll
    for (int i = 0; i < 32; i += 8)
        tile[ty + i][tx] = W[(size_t)(k0 + ty + i) * D_ + n0 + tx];
    __syncthreads();
#pragma unroll
    for (int i = 0; i < 32; i += 8) {
        float v = tile[tx][ty + i];
        __nv_bfloat16 h, l;
        split1(v, h, l);
        const size_t idx = tm_idx(n0 + ty + i, k0 + tx, D_);
        g_Wh[z][idx] = h;
        g_Wl[z][idx] = l;
    }
}

// ---------------------------------------------------------------------------
// Tensor-core GEMM (bf16x3): 128x128 tile, 256 threads, 2 CTAs/SM,
// cp.async.bulk double-buffered.
// smem: [mb0|mb1 (128B)] [stage0 32KB: Ah|Al|Bh|Bl] [stage1 32KB]
// ---------------------------------------------------------------------------
#define GSTB 32768
#define GEMM_SMEM (128 + 2 * GSTB)

template <int MODE>
__global__ __launch_bounds__(256, 2)
void gemm_tc(const float* __restrict__ bias0, const float* __restrict__ bias1,
             const float* __restrict__ bias2, float* __restrict__ Cout)
{
    extern __shared__ char smc[];

    const int z = (MODE == 1) ? blockIdx.z : 0;
    const __nv_bfloat16* Ah = g_Ah[z];
    const __nv_bfloat16* Al = g_Al[z];
    const __nv_bfloat16* Wh = g_Wh[(MODE == 0) ? 3 : z];
    const __nv_bfloat16* Wl = g_Wl[(MODE == 0) ? 3 : z];
    const float* bias = (MODE == 0) ? bias0 : (z == 0) ? bias0 : (z == 1) ? bias1 : bias2;
    const float oscale = (MODE == 1 && z == 0) ? QSCALE : 1.0f;

    const int tid = threadIdx.x;
    const int bm = blockIdx.y * 128;
    const int bn = blockIdx.x * 128;

    const int lane = tid & 31;
    const int wid  = tid >> 5;
    const int wm   = wid & 3;         // 4 m-warps (32 rows each)
    const int wn   = wid >> 2;        // 2 n-warps (64 cols each)
    const int g    = lane >> 2;
    const int tg   = lane & 3;

    const uint32_t smb = smem_u32(smc);
    const uint32_t mb0 = smb, mb1 = smb + 8;

    if (tid == 0) {
        MBAR_INIT(mb0, 1);
        MBAR_INIT(mb1, 1);
    }
    __syncthreads();

    const int rrA = (lane & 7) + ((lane >> 3) & 1) * 8;
    const int khA = lane >> 4;
    const int rrB = (lane & 7) + (lane >> 4) * 8;
    const int khB = (lane >> 3) & 1;

    auto issue = [&](int t) {
        const uint32_t mb = (t & 1) ? mb1 : mb0;
        const uint32_t base = smb + 128 + (uint32_t)(t & 1) * GSTB;
        MBAR_EXPECT_TX(mb, GSTB);
        bulk_g2s(base,         Ah + ((size_t)t * M_ + bm) * 32, 8192, mb);
        bulk_g2s(base + 8192,  Al + ((size_t)t * M_ + bm) * 32, 8192, mb);
        bulk_g2s(base + 16384, Wh + ((size_t)t * D_ + bn) * 32, 8192, mb);
        bulk_g2s(base + 24576, Wl + ((size_t)t * D_ + bn) * 32, 8192, mb);
    };

    float acc[2][8][4];
#pragma unroll
    for (int mt = 0; mt < 2; mt++)
#pragma unroll
        for (int nt = 0; nt < 8; nt++)
#pragma unroll
            for (int i = 0; i < 4; i++) acc[mt][nt][i] = 0.f;

    if (tid == 0) issue(0);

    const int NT = D_ / 32;
    for (int t = 0; t < NT; t++) {
        if (t + 1 < NT) {
            __syncthreads();
            if (tid == 0) issue(t + 1);
        }
        MBAR_WAIT((t & 1) ? mb1 : mb0, (t >> 1) & 1);

        const uint32_t base = smb + 128 + (uint32_t)(t & 1) * GSTB;
        const uint32_t bAh = base;
        const uint32_t bAl = base + 8192;
        const uint32_t bBh = base + 16384;
        const uint32_t bBl = base + 24576;

#pragma unroll
        for (int kk = 0; kk < 32; kk += 16) {
            uint32_t ah[2][4], al[2][4];
#pragma unroll
            for (int mt = 0; mt < 2; mt++) {
                const int row = wm * 32 + mt * 16 + rrA;
                const int sc = ((kk >> 3) + khA) ^ ((row >> 1) & 3);
                const uint32_t off = (uint32_t)(row * 64 + sc * 16);
                ldsm4(ah[mt], bAh + off);
                ldsm4(al[mt], bAl + off);
            }
#pragma unroll
            for (int ntp = 0; ntp < 4; ntp++) {
                const int row = wn * 64 + ntp * 16 + rrB;
                const int sc = ((kk >> 3) + khB) ^ ((row >> 1) & 3);
                const uint32_t off = (uint32_t)(row * 64 + sc * 16);
                uint32_t bh4[4], bl4[4];
                ldsm4(bh4, bBh + off);
                ldsm4(bl4, bBl + off);
                mma16816(acc[0][2 * ntp],     ah[0], &bh4[0]);
                mma16816(acc[1][2 * ntp],     ah[1], &bh4[0]);
                mma16816(acc[0][2 * ntp + 1], ah[0], &bh4[2]);
                mma16816(acc[1][2 * ntp + 1], ah[1], &bh4[2]);
                mma16816(acc[0][2 * ntp],     ah[0], &bl4[0]);
                mma16816(acc[1][2 * ntp],     ah[1], &bl4[0]);
                mma16816(acc[0][2 * ntp + 1], ah[0], &bl4[2]);
                mma16816(acc[1][2 * ntp + 1], ah[1], &bl4[2]);
                mma16816(acc[0][2 * ntp],     al[0], &bh4[0]);
                mma16816(acc[1][2 * ntp],     al[1], &bh4[0]);
                mma16816(acc[0][2 * ntp + 1], al[0], &bh4[2]);
                mma16816(acc[1][2 * ntp + 1], al[1], &bh4[2]);
            }
        }
    }

    // Epilogue
#pragma unroll
    for (int mt = 0; mt < 2; mt++) {
#pragma unroll
        for (int nt = 0; nt < 8; nt++) {
            const int col = bn + wn * 64 + nt * 8 + tg * 2;
            const float b0 = bias[col], b1 = bias[col + 1];
#pragma unroll
            for (int half = 0; half < 2; half++) {
                const int row = bm + wm * 32 + mt * 16 + g + half * 8;
                float vx = acc[mt][nt][half * 2 + 0] + b0;
                float vy = acc[mt][nt][half * 2 + 1] + b1;
                if (MODE == 0) {
                    *reinterpret_cast<float2*>(Cout + (size_t)row * D_ + col) =
                        make_float2(vx, vy);
                } else {
                    vx *= oscale; vy *= oscale;
                    __nv_bfloat16 hx, lx, hy, ly;
                    split1(vx, hx, lx);
                    split1(vy, hy, ly);
                    const int b  = row >> 11;
                    const int s  = row & (S_ - 1);
                    const int h  = col >> 6;
                    const int dk = col & (DK_ - 1);
                    const size_t bh = (size_t)b * H_ + h;
                    if (z == 0) {
                        const size_t idx = (bh * S_ + s) * DK_ + dk;
                        *reinterpret_cast<uint32_t*>(g_qh + idx) =
                            ((uint32_t)__bfloat16_as_ushort(hy) << 16) | __bfloat16_as_ushort(hx);
                        *reinterpret_cast<uint32_t*>(g_ql + idx) =
                            ((uint32_t)__bfloat16_as_ushort(ly) << 16) | __bfloat16_as_ushort(lx);
                    } else if (z == 1) {
                        const size_t idx = bh * S_ * DK_ + tm_idx(s, dk, S_);
                        *reinterpret_cast<uint32_t*>(g_kh + idx) =
                            ((uint32_t)__bfloat16_as_ushort(hy) << 16) | __bfloat16_as_ushort(hx);
                        *reinterpret_cast<uint32_t*>(g_kl + idx) =
                            ((uint32_t)__bfloat16_as_ushort(ly) << 16) | __bfloat16_as_ushort(lx);
                    } else {
                        const size_t i0 = bh * DK_ * S_ + tm_idx(dk,     s, DK_);
                        const size_t i1 = bh * DK_ * S_ + tm_idx(dk + 1, s, DK_);
                        g_vh[i0] = hx;
                        g_vh[i1] = hy;
                        g_vl[i0] = lx;
                        g_vl[i1] = ly;
                    }
                }
            }
        }
    }
}

// ---------------------------------------------------------------------------
// Tensor-core flash attention (bf16x3) — byte-identical to R15.
// ---------------------------------------------------------------------------
#define ATB 32768
#define ATTN_SMEM (128 + 2 * ATB + S_ * 4)

__global__ __launch_bounds__(256, 2)
void attn_tc(const int* __restrict__ mask)
{
    extern __shared__ char smc[];
    float* smadd = reinterpret_cast<float*>(smc + 128 + 2 * ATB);

    const int bh = blockIdx.y;
    const int b  = bh >> 4;
    const int h  = bh & 15;
    const int tid  = threadIdx.x;
    const int lane = tid & 31;
    const int wid  = tid >> 5;
    const int g    = lane >> 2;
    const int tg   = lane & 3;
    const int qrow0 = blockIdx.x * 128 + wid * 16;

    const size_t kbh = (size_t)bh * S_ * DK_;
    const size_t vbh = (size_t)bh * DK_ * S_;

    const uint32_t smb = smem_u32(smc);
    const uint32_t mb0 = smb, mb1 = smb + 8;

    if (tid == 0) {
        MBAR_INIT(mb0, 1);
        MBAR_INIT(mb1, 1);
    }
    __syncthreads();

    const int rrB = (lane & 7) + (lane >> 4) * 8;
    const int khB = (lane >> 3) & 1;

    auto issue = [&](int t) {
        const uint32_t mb = (t & 1) ? mb1 : mb0;
        const uint32_t base = smb + 128 + (uint32_t)(t & 1) * ATB;
        const int kt = t * 64;
        MBAR_EXPECT_TX(mb, ATB);
        bulk_g2s(base,          g_kh + kbh + (size_t)(0 * S_ + kt) * 32, 4096, mb);
        bulk_g2s(base + 4096,   g_kh + kbh + (size_t)(1 * S_ + kt) * 32, 4096, mb);
        bulk_g2s(base + 8192,   g_kl + kbh + (size_t)(0 * S_ + kt) * 32, 4096, mb);
        bulk_g2s(base + 12288,  g_kl + kbh + (size_t)(1 * S_ + kt) * 32, 4096, mb);
        bulk_g2s(base + 16384,  g_vh + vbh + (size_t)(2 * t + 0) * DK_ * 32, 4096, mb);
        bulk_g2s(base + 20480,  g_vh + vbh + (size_t)(2 * t + 1) * DK_ * 32, 4096, mb);
        bulk_g2s(base + 24576,  g_vl + vbh + (size_t)(2 * t + 0) * DK_ * 32, 4096, mb);
        bulk_g2s(base + 28672,  g_vl + vbh + (size_t)(2 * t + 1) * DK_ * 32, 4096, mb);
    };

    if (tid == 0) issue(0);

#pragma unroll
    for (int i = 0; i < S_ / 256; i++)
        smadd[tid + i * 256] = (mask[b * S_ + tid + i * 256] == 0) ? -1e30f : 0.f;

    const size_t qoff = (size_t)bh * S_ * DK_;
    uint32_t aqh[4][4], aql[4][4];
#pragma unroll
    for (int ks = 0; ks < 4; ks++) {
        const int c0 = ks * 16 + 2 * tg;
        const size_t r0 = qoff + (size_t)(qrow0 + g) * DK_;
        const size_t r1 = qoff + (size_t)(qrow0 + g + 8) * DK_;
        aqh[ks][0] = *reinterpret_cast<const uint32_t*>(g_qh + r0 + c0);
        aqh[ks][1] = *reinterpret_cast<const uint32_t*>(g_qh + r1 + c0);
        aqh[ks][2] = *reinterpret_cast<const uint32_t*>(g_qh + r0 + c0 + 8);
        aqh[ks][3] = *reinterpret_cast<const uint32_t*>(g_qh + r1 + c0 + 8);
        aql[ks][0] = *reinterpret_cast<const uint32_t*>(g_ql + r0 + c0);
        aql[ks][1] = *reinterpret_cast<const uint32_t*>(g_ql + r1 + c0);
        aql[ks][2] = *reinterpret_cast<const uint32_t*>(g_ql + r0 + c0 + 8);
        aql[ks][3] = *reinterpret_cast<const uint32_t*>(g_ql + r1 + c0 + 8);
    }

    float accO[8][4];
#pragma unroll
    for (int i = 0; i < 8; i++)
#pragma unroll
        for (int j = 0; j < 4; j++) accO[i][j] = 0.f;

    float sum0 = 0.f, sum1 = 0.f;

    const int NTILES = S_ / 64;
    for (int t = 0; t < NTILES; t++) {
        const int kt = t * 64;
        if (t + 1 < NTILES) {
            __syncthreads();
            if (tid == 0) issue(t + 1);
        }
        MBAR_WAIT((t & 1) ? mb1 : mb0, (t >> 1) & 1);

        const uint32_t base = smb + 128 + (uint32_t)(t & 1) * ATB;
        const uint32_t bKh = base;
        const uint32_t bKl = base + 8192;
        const uint32_t bVh = base + 16384;
        const uint32_t bVl = base + 24576;

        float acc[8][4];
#pragma unroll
        for (int i = 0; i < 8; i++)
#pragma unroll
            for (int j = 0; j < 4; j++) acc[i][j] = 0.f;

#pragma unroll
        for (int ks = 0; ks < 4; ks++)
#pragma unroll
            for (int ntp = 0; ntp < 4; ntp++) {
                const int row = ntp * 16 + rrB;
                const int kdk = ks * 16 + khB * 8;
                const int sc = ((kdk >> 3) & 3) ^ ((row >> 1) & 3);
                const uint32_t off = (uint32_t)((kdk >> 5) * 4096 + row * 64 + sc * 16);
                uint32_t kh4[4], kl4[4];
                ldsm4(kh4, bKh + off);
                ldsm4(kl4, bKl + off);
                mma16816(acc[2 * ntp],     aqh[ks], &kh4[0]);
                mma16816(acc[2 * ntp + 1], aqh[ks], &kh4[2]);
                mma16816(acc[2 * ntp],     aqh[ks], &kl4[0]);
                mma16816(acc[2 * ntp + 1], aqh[ks], &kl4[2]);
                mma16816(acc[2 * ntp],     aql[ks], &kh4[0]);
                mma16816(acc[2 * ntp + 1], aql[ks], &kh4[2]);
            }

#pragma unroll
        for (int kb2 = 0; kb2 < 4; kb2++) {
            uint32_t ph[4], pl[4];
#pragma unroll
            for (int half = 0; half < 2; half++) {
                const int nt = 2 * kb2 + half;
                const float ma = smadd[kt + nt * 8 + 2 * tg];
                const float mb = smadd[kt + nt * 8 + 2 * tg + 1];
                const float p0 = fast_exp2(acc[nt][0] + ma);
                const float p1 = fast_exp2(acc[nt][1] + mb);
                const float p2 = fast_exp2(acc[nt][2] + ma);
                const float p3 = fast_exp2(acc[nt][3] + mb);
                sum0 += p0 + p1;
                sum1 += p2 + p3;
                const uint32_t h01 = pack_bf16(p0, p1);
                const uint32_t h23 = pack_bf16(p2, p3);
                const float q0 = p0 - __uint_as_float(h01 << 16);
                const float q1 = p1 - __uint_as_float(h01 & 0xffff0000u);
                const float q2 = p2 - __uint_as_float(h23 << 16);
                const float q3 = p3 - __uint_as_float(h23 & 0xffff0000u);
                ph[2 * half + 0] = h01;
                ph[2 * half + 1] = h23;
                pl[2 * half + 0] = pack_bf16(q0, q1);
                pl[2 * half + 1] = pack_bf16(q2, q3);
            }
#pragma unroll
            for (int ntp = 0; ntp < 4; ntp++) {
                const int row = ntp * 16 + rrB;
                const int kss = kb2 * 16 + khB * 8;
                const int sc = ((kss >> 3) & 3) ^ ((row >> 1) & 3);
                const uint32_t off = (uint32_t)((kss >> 5) * 4096 + row * 64 + sc * 16);
                uint32_t vh4[4], vl4[4];
                ldsm4(vh4, bVh + off);
                ldsm4(vl4, bVl + off);
                mma16816(accO[2 * ntp],     ph, &vh4[0]);
                mma16816(accO[2 * ntp + 1], ph, &vh4[2]);
                mma16816(accO[2 * ntp],     ph, &vl4[0]);
                mma16816(accO[2 * ntp + 1], ph, &vl4[2]);
                mma16816(accO[2 * ntp],     pl, &vh4[0]);
                mma16816(accO[2 * ntp + 1], pl, &vh4[2]);
            }
        }
    }

    sum0 += __shfl_xor_sync(0xffffffffu, sum0, 1);
    sum0 += __shfl_xor_sync(0xffffffffu, sum0, 2);
    sum1 += __shfl_xor_sync(0xffffffffu, sum1, 1);
    sum1 += __shfl_xor_sync(0xffffffffu, sum1, 2);

    const float i0 = 1.f / sum0;
    const float i1 = 1.f / sum1;
    const int m0 = b * S_ + qrow0 + g;
    const int m1 = m0 + 8;
#pragma unroll
    for (int nt2 = 0; nt2 < 8; nt2++) {
        const int col = h * DK_ + nt2 * 8 + 2 * tg;
        float vx0 = accO[nt2][0] * i0, vy0 = accO[nt2][1] * i0;
        float vx1 = accO[nt2][2] * i1, vy1 = accO[nt2][3] * i1;
        __nv_bfloat16 hx, lx, hy, ly;
        const size_t p0 = tm_idx(m0, col, M_);
        split1(vx0, hx, lx); split1(vy0, hy, ly);
        *reinterpret_cast<uint32_t*>(g_Ah[0] + p0) =
            ((uint32_t)__bfloat16_as_ushort(hy) << 16) | __bfloat16_as_ushort(hx);
        *reinterpret_cast<uint32_t*>(g_Al[0] + p0) =
            ((uint32_t)__bfloat16_as_ushort(ly) << 16) | __bfloat16_as_ushort(lx);
        const size_t p1 = tm_idx(m1, col, M_);
        split1(vx1, hx, lx); split1(vy1, hy, ly);
        *reinterpret_cast<uint32_t*>(g_Ah[0] + p1) =
            ((uint32_t)__bfloat16_as_ushort(hy) << 16) | __bfloat16_as_ushort(hx);
        *reinterpret_cast<uint32_t*>(g_Al[0] + p1) =
            ((uint32_t)__bfloat16_as_ushort(ly) << 16) | __bfloat16_as_ushort(lx);
    }
}

// ---------------------------------------------------------------------------
// Launch
// ---------------------------------------------------------------------------
extern "C" void kernel_launch(void* const* d_in, const int* in_sizes, int n_in,
                              void* d_out, int out_size)
{
    const float* query = (const float*)d_in[0];
    const float* key   = (const float*)d_in[1];
    const float* value = (const float*)d_in[2];
    const int*   mask  = (const int*)  d_in[3];
    const float* Wq = (const float*)d_in[4];
    const float* bq = (const float*)d_in[5];
    const float* Wk = (const float*)d_in[6];
    const float* bk = (const float*)d_in[7];
    const float* Wv = (const float*)d_in[8];
    const float* bv = (const float*)d_in[9];
    const float* Wo = (const float*)d_in[10];
    const float* bo = (const float*)d_in[11];
    float* out = (float*)d_out;

    cudaFuncSetAttribute(gemm_tc<1>, cudaFuncAttributeMaxDynamicSharedMemorySize, GEMM_SMEM);
    cudaFuncSetAttribute(gemm_tc<0>, cudaFuncAttributeMaxDynamicSharedMemorySize, GEMM_SMEM);
    cudaFuncSetAttribute(attn_tc,    cudaFuncAttributeMaxDynamicSharedMemorySize, ATTN_SMEM);

    dim3 wtg(D_ / 32, D_ / 32, 4);
    split_wt_all<<<wtg, dim3(32, 8)>>>(Wq, Wk, Wv, Wo);
    dim3 sag((M_ * D_ / 4) / 256, 3);
    split_act_all<<<sag, 256>>>(query, key, value);

    dim3 gqkv(D_ / 128, M_ / 128, 3);   // (8, 32, 3) = 768 CTAs
    gemm_tc<1><<<gqkv, 256, GEMM_SMEM>>>(bq, bk, bv, nullptr);

    dim3 agrid(S_ / 128, B_ * H_);
    attn_tc<<<agrid, 256, ATTN_SMEM>>>(mask);

    dim3 gout(D_ / 128, M_ / 128);      // (8, 32)
    gemm_tc<0><<<gout, 256, GEMM_SMEM>>>(bo, nullptr, nullptr, out);
}

// round 17
// speedup vs baseline: 1.3098x; 1.0068x over previous
#include <cuda_runtime.h>
#include <cuda_bf16.h>
#include <stdint.h>

// Problem constants
#define B_  2
#define S_  2048
#define D_  1024
#define H_  16
#define DK_ 64
#define M_  (B_ * S_)

#define QSCALE (0.125f * 1.44269504088896340736f)

// ---------------------------------------------------------------------------
// Scratch (device globals — no allocations allowed)
// Tile-major swizzled layouts (k-chunk outer, 32-k inner with XOR sub-chunk):
//   elem (row, k) -> ((k>>5)*NROWS + row)*32 + (((k&31)>>3) ^ ((row>>1)&3))*8 + (k&7)
// ---------------------------------------------------------------------------
__device__ __nv_bfloat16 g_Ah[3][M_ * D_];
__device__ __nv_bfloat16 g_Al[3][M_ * D_];
__device__ __nv_bfloat16 g_Wh[4][D_ * D_];
__device__ __nv_bfloat16 g_Wl[4][D_ * D_];

__device__ __nv_bfloat16 g_qh[B_ * H_ * S_ * DK_];  // [bh][s][dk] row-major, pre-scaled
__device__ __nv_bfloat16 g_ql[B_ * H_ * S_ * DK_];
__device__ __nv_bfloat16 g_kh[B_ * H_ * S_ * DK_];  // tile-major per bh (row=s,k=dk)
__device__ __nv_bfloat16 g_kl[B_ * H_ * S_ * DK_];
__device__ __nv_bfloat16 g_vh[B_ * H_ * DK_ * S_];  // tile-major per bh (row=dk,k=s)
__device__ __nv_bfloat16 g_vl[B_ * H_ * DK_ * S_];

// ---------------------------------------------------------------------------
// Helpers
// ---------------------------------------------------------------------------
__device__ __forceinline__ size_t tm_idx(int row, int k, int nrows) {
    const int chunk = k >> 5;
    const int cc = k & 31;
    const int sc = (cc >> 3) ^ ((row >> 1) & 3);
    return ((size_t)chunk * nrows + row) * 32 + sc * 8 + (cc & 7);
}

__device__ __forceinline__ void split1(float x, __nv_bfloat16& h, __nv_bfloat16& l) {
    h = __float2bfloat16_rn(x);
    l = __float2bfloat16_rn(x - __bfloat162float(h));
}

__device__ __forceinline__ uint32_t pack_bf16(float lo, float hi) {
    uint32_t r;
    asm("cvt.rn.bf16x2.f32 %0, %1, %2;" : "=r"(r) : "f"(hi), "f"(lo));
    return r;
}

__device__ __forceinline__ float fast_exp2(float x) {
    float r;
    asm("ex2.approx.f32 %0, %1;" : "=f"(r) : "f"(x));
    return r;
}

__device__ __forceinline__ void mma16816(float* c, const uint32_t* a, const uint32_t* b)
{
    asm("mma.sync.aligned.m16n8k16.row.col.f32.bf16.bf16.f32 "
        "{%0,%1,%2,%3},{%4,%5,%6,%7},{%8,%9},{%0,%1,%2,%3};"
        : "+f"(c[0]), "+f"(c[1]), "+f"(c[2]), "+f"(c[3])
        : "r"(a[0]), "r"(a[1]), "r"(a[2]), "r"(a[3]), "r"(b[0]), "r"(b[1]));
}

__device__ __forceinline__ void ldsm4(uint32_t* r, uint32_t addr)
{
    asm volatile("ldmatrix.sync.aligned.m8n8.x4.shared.b16 {%0,%1,%2,%3}, [%4];"
        : "=r"(r[0]), "=r"(r[1]), "=r"(r[2]), "=r"(r[3]) : "r"(addr));
}

__device__ __forceinline__ uint32_t smem_u32(const void* p) {
    return (uint32_t)__cvta_generic_to_shared(p);
}

__device__ __forceinline__ void bulk_g2s(uint32_t dst, const void* src,
                                         uint32_t bytes, uint32_t mbar)
{
    asm volatile("cp.async.bulk.shared::cta.global.mbarrier::complete_tx::bytes "
                 "[%0], [%1], %2, [%3];"
        :: "r"(dst), "l"(src), "r"(bytes), "r"(mbar) : "memory");
}

#define MBAR_INIT(mbar, count) \
    asm volatile("mbarrier.init.shared.b64 [%0], %1;" \
        :: "r"((uint32_t)(mbar)), "r"((uint32_t)(count)) : "memory")
#define MBAR_EXPECT_TX(mbar, tx) \
    asm volatile("mbarrier.arrive.expect_tx.shared.b64 _, [%0], %1;" \
        :: "r"((uint32_t)(mbar)), "r"((uint32_t)(tx)) : "memory")
#define MBAR_WAIT(mbar, parity) do { \
    uint32_t _m = (uint32_t)(mbar); uint32_t _p = (uint32_t)(parity); uint32_t _d; \
    asm volatile("{\n\t.reg .pred p;\n\t" \
        "mbarrier.try_wait.parity.acquire.cta.shared::cta.b64 p, [%1], %2;\n\t" \
        "selp.b32 %0, 1, 0, p;\n\t}" : "=r"(_d) : "r"(_m), "r"(_p) : "memory"); \
    if (!_d) { \
        asm volatile("{\n\t.reg .pred P1;\n\t" \
            "WL_%=:\n\t" \
            "mbarrier.try_wait.parity.acquire.cta.shared::cta.b64 P1, [%0], %1, 0x989680;\n\t" \
            "@P1 bra.uni WD_%=;\n\tbra.uni WL_%=;\n\tWD_%=:\n\t}" \
            :: "r"(_m), "r"(_p) : "memory"); \
    } \
} while (0)

// ---------------------------------------------------------------------------
// Split kernels — tile-major swizzled layout (unchanged).
// ---------------------------------------------------------------------------
__global__ __launch_bounds__(256)
void split_act_all(const float* __restrict__ q, const float* __restrict__ k,
                   const float* __restrict__ v)
{
    const int z = blockIdx.y;
    const float* src = (z == 0) ? q : (z == 1) ? k : v;
    const int i = blockIdx.x * 256 + threadIdx.x;
    const int m  = i >> 8;
    const int k0 = (i & 255) * 4;
    float4 val = reinterpret_cast<const float4*>(src)[i];
    __nv_bfloat16 h0, h1, h2, h3, l0, l1, l2, l3;
    split1(val.x, h0, l0); split1(val.y, h1, l1);
    split1(val.z, h2, l2); split1(val.w, h3, l3);
    uint2 hp, lp;
    hp.x = ((uint32_t)__bfloat16_as_ushort(h1) << 16) | __bfloat16_as_ushort(h0);
    hp.y = ((uint32_t)__bfloat16_as_ushort(h3) << 16) | __bfloat16_as_ushort(h2);
    lp.x = ((uint32_t)__bfloat16_as_ushort(l1) << 16) | __bfloat16_as_ushort(l0);
    lp.y = ((uint32_t)__bfloat16_as_ushort(l3) << 16) | __bfloat16_as_ushort(l2);
    const size_t pos = tm_idx(m, k0, M_);
    *reinterpret_cast<uint2*>(g_Ah[z] + pos) = hp;
    *reinterpret_cast<uint2*>(g_Al[z] + pos) = lp;
}

__global__ __launch_bounds__(256)
void split_wt_all(const float* __restrict__ Wq, const float* __restrict__ Wk,
                  const float* __restrict__ Wv, const float* __restrict__ Wo)
{
    __shared__ float tile[32][33];
    const int z = blockIdx.z;
    const float* W = (z == 0) ? Wq : (z == 1) ? Wk : (z == 2) ? Wv : Wo;
    const int tx = threadIdx.x;
    const int ty = threadIdx.y;
    const int n0 = blockIdx.x * 32;
    const int k0 = blockIdx.y * 32;
#pragma unroll
    for (int i = 0; i < 32; i += 8)
        tile[ty + i][tx] = W[(size_t)(k0 + ty + i) * D_ + n0 + tx];
    __syncthreads();
#pragma unroll
    for (int i = 0; i < 32; i += 8) {
        float v = tile[tx][ty + i];
        __nv_bfloat16 h, l;
        split1(v, h, l);
        const size_t idx = tm_idx(n0 + ty + i, k0 + tx, D_);
        g_Wh[z][idx] = h;
        g_Wl[z][idx] = l;
    }
}

// ---------------------------------------------------------------------------
// Tensor-core GEMM (bf16x3): 128x128 tile, 256 threads, 2 CTAs/SM,
// cp.async.bulk double-buffered — byte-identical to R16.
// ---------------------------------------------------------------------------
#define GSTB 32768
#define GEMM_SMEM (128 + 2 * GSTB)

template <int MODE>
__global__ __launch_bounds__(256, 2)
void gemm_tc(const float* __restrict__ bias0, const float* __restrict__ bias1,
             const float* __restrict__ bias2, float* __restrict__ Cout)
{
    extern __shared__ char smc[];

    const int z = (MODE == 1) ? blockIdx.z : 0;
    const __nv_bfloat16* Ah = g_Ah[z];
    const __nv_bfloat16* Al = g_Al[z];
    const __nv_bfloat16* Wh = g_Wh[(MODE == 0) ? 3 : z];
    const __nv_bfloat16* Wl = g_Wl[(MODE == 0) ? 3 : z];
    const float* bias = (MODE == 0) ? bias0 : (z == 0) ? bias0 : (z == 1) ? bias1 : bias2;
    const float oscale = (MODE == 1 && z == 0) ? QSCALE : 1.0f;

    const int tid = threadIdx.x;
    const int bm = blockIdx.y * 128;
    const int bn = blockIdx.x * 128;

    const int lane = tid & 31;
    const int wid  = tid >> 5;
    const int wm   = wid & 3;
    const int wn   = wid >> 2;
    const int g    = lane >> 2;
    const int tg   = lane & 3;

    const uint32_t smb = smem_u32(smc);
    const uint32_t mb0 = smb, mb1 = smb + 8;

    if (tid == 0) {
        MBAR_INIT(mb0, 1);
        MBAR_INIT(mb1, 1);
    }
    __syncthreads();

    const int rrA = (lane & 7) + ((lane >> 3) & 1) * 8;
    const int khA = lane >> 4;
    const int rrB = (lane & 7) + (lane >> 4) * 8;
    const int khB = (lane >> 3) & 1;

    auto issue = [&](int t) {
        const uint32_t mb = (t & 1) ? mb1 : mb0;
        const uint32_t base = smb + 128 + (uint32_t)(t & 1) * GSTB;
        MBAR_EXPECT_TX(mb, GSTB);
        bulk_g2s(base,         Ah + ((size_t)t * M_ + bm) * 32, 8192, mb);
        bulk_g2s(base + 8192,  Al + ((size_t)t * M_ + bm) * 32, 8192, mb);
        bulk_g2s(base + 16384, Wh + ((size_t)t * D_ + bn) * 32, 8192, mb);
        bulk_g2s(base + 24576, Wl + ((size_t)t * D_ + bn) * 32, 8192, mb);
    };

    float acc[2][8][4];
#pragma unroll
    for (int mt = 0; mt < 2; mt++)
#pragma unroll
        for (int nt = 0; nt < 8; nt++)
#pragma unroll
            for (int i = 0; i < 4; i++) acc[mt][nt][i] = 0.f;

    if (tid == 0) issue(0);

    const int NT = D_ / 32;
    for (int t = 0; t < NT; t++) {
        if (t + 1 < NT) {
            __syncthreads();
            if (tid == 0) issue(t + 1);
        }
        MBAR_WAIT((t & 1) ? mb1 : mb0, (t >> 1) & 1);

        const uint32_t base = smb + 128 + (uint32_t)(t & 1) * GSTB;
        const uint32_t bAh = base;
        const uint32_t bAl = base + 8192;
        const uint32_t bBh = base + 16384;
        const uint32_t bBl = base + 24576;

#pragma unroll
        for (int kk = 0; kk < 32; kk += 16) {
            uint32_t ah[2][4], al[2][4];
#pragma unroll
            for (int mt = 0; mt < 2; mt++) {
                const int row = wm * 32 + mt * 16 + rrA;
                const int sc = ((kk >> 3) + khA) ^ ((row >> 1) & 3);
                const uint32_t off = (uint32_t)(row * 64 + sc * 16);
                ldsm4(ah[mt], bAh + off);
                ldsm4(al[mt], bAl + off);
            }
#pragma unroll
            for (int ntp = 0; ntp < 4; ntp++) {
                const int row = wn * 64 + ntp * 16 + rrB;
                const int sc = ((kk >> 3) + khB) ^ ((row >> 1) & 3);
                const uint32_t off = (uint32_t)(row * 64 + sc * 16);
                uint32_t bh4[4], bl4[4];
                ldsm4(bh4, bBh + off);
                ldsm4(bl4, bBl + off);
                mma16816(acc[0][2 * ntp],     ah[0], &bh4[0]);
                mma16816(acc[1][2 * ntp],     ah[1], &bh4[0]);
                mma16816(acc[0][2 * ntp + 1], ah[0], &bh4[2]);
                mma16816(acc[1][2 * ntp + 1], ah[1], &bh4[2]);
                mma16816(acc[0][2 * ntp],     ah[0], &bl4[0]);
                mma16816(acc[1][2 * ntp],     ah[1], &bl4[0]);
                mma16816(acc[0][2 * ntp + 1], ah[0], &bl4[2]);
                mma16816(acc[1][2 * ntp + 1], ah[1], &bl4[2]);
                mma16816(acc[0][2 * ntp],     al[0], &bh4[0]);
                mma16816(acc[1][2 * ntp],     al[1], &bh4[0]);
                mma16816(acc[0][2 * ntp + 1], al[0], &bh4[2]);
                mma16816(acc[1][2 * ntp + 1], al[1], &bh4[2]);
            }
        }
    }

    // Epilogue
#pragma unroll
    for (int mt = 0; mt < 2; mt++) {
#pragma unroll
        for (int nt = 0; nt < 8; nt++) {
            const int col = bn + wn * 64 + nt * 8 + tg * 2;
            const float b0 = bias[col], b1 = bias[col + 1];
#pragma unroll
            for (int half = 0; half < 2; half++) {
                const int row = bm + wm * 32 + mt * 16 + g + half * 8;
                float vx = acc[mt][nt][half * 2 + 0] + b0;
                float vy = acc[mt][nt][half * 2 + 1] + b1;
                if (MODE == 0) {
                    *reinterpret_cast<float2*>(Cout + (size_t)row * D_ + col) =
                        make_float2(vx, vy);
                } else {
                    vx *= oscale; vy *= oscale;
                    __nv_bfloat16 hx, lx, hy, ly;
                    split1(vx, hx, lx);
                    split1(vy, hy, ly);
                    const int b  = row >> 11;
                    const int s  = row & (S_ - 1);
                    const int h  = col >> 6;
                    const int dk = col & (DK_ - 1);
                    const size_t bh = (size_t)b * H_ + h;
                    if (z == 0) {
                        const size_t idx = (bh * S_ + s) * DK_ + dk;
                        *reinterpret_cast<uint32_t*>(g_qh + idx) =
                            ((uint32_t)__bfloat16_as_ushort(hy) << 16) | __bfloat16_as_ushort(hx);
                        *reinterpret_cast<uint32_t*>(g_ql + idx) =
                            ((uint32_t)__bfloat16_as_ushort(ly) << 16) | __bfloat16_as_ushort(lx);
                    } else if (z == 1) {
                        const size_t idx = bh * S_ * DK_ + tm_idx(s, dk, S_);
                        *reinterpret_cast<uint32_t*>(g_kh + idx) =
                            ((uint32_t)__bfloat16_as_ushort(hy) << 16) | __bfloat16_as_ushort(hx);
                        *reinterpret_cast<uint32_t*>(g_kl + idx) =
                            ((uint32_t)__bfloat16_as_ushort(ly) << 16) | __bfloat16_as_ushort(lx);
                    } else {
                        const size_t i0 = bh * DK_ * S_ + tm_idx(dk,     s, DK_);
                        const size_t i1 = bh * DK_ * S_ + tm_idx(dk + 1, s, DK_);
                        g_vh[i0] = hx;
                        g_vh[i1] = hy;
                        g_vl[i0] = lx;
                        g_vl[i1] = ly;
                    }
                }
            }
        }
    }
}

// ---------------------------------------------------------------------------
// Tensor-core flash attention (bf16x3): per-key-group interleaved
// QK -> softmax -> PV (16-key granularity). Same arithmetic as R16; only
// instruction scheduling changes — exp2/pack of group kg issues in the
// shadow of PV(kg-1) and QK(kg+1) tensor work.
// ---------------------------------------------------------------------------
#define ATB 32768
#define ATTN_SMEM (128 + 2 * ATB + S_ * 4)

__global__ __launch_bounds__(256, 2)
void attn_tc(const int* __restrict__ mask)
{
    extern __shared__ char smc[];
    float* smadd = reinterpret_cast<float*>(smc + 128 + 2 * ATB);

    const int bh = blockIdx.y;
    const int b  = bh >> 4;
    const int h  = bh & 15;
    const int tid  = threadIdx.x;
    const int lane = tid & 31;
    const int wid  = tid >> 5;
    const int g    = lane >> 2;
    const int tg   = lane & 3;
    const int qrow0 = blockIdx.x * 128 + wid * 16;

    const size_t kbh = (size_t)bh * S_ * DK_;
    const size_t vbh = (size_t)bh * DK_ * S_;

    const uint32_t smb = smem_u32(smc);
    const uint32_t mb0 = smb, mb1 = smb + 8;

    if (tid == 0) {
        MBAR_INIT(mb0, 1);
        MBAR_INIT(mb1, 1);
    }
    __syncthreads();

    const int rrB = (lane & 7) + (lane >> 4) * 8;
    const int khB = (lane >> 3) & 1;

    auto issue = [&](int t) {
        const uint32_t mb = (t & 1) ? mb1 : mb0;
        const uint32_t base = smb + 128 + (uint32_t)(t & 1) * ATB;
        const int kt = t * 64;
        MBAR_EXPECT_TX(mb, ATB);
        bulk_g2s(base,          g_kh + kbh + (size_t)(0 * S_ + kt) * 32, 4096, mb);
        bulk_g2s(base + 4096,   g_kh + kbh + (size_t)(1 * S_ + kt) * 32, 4096, mb);
        bulk_g2s(base + 8192,   g_kl + kbh + (size_t)(0 * S_ + kt) * 32, 4096, mb);
        bulk_g2s(base + 12288,  g_kl + kbh + (size_t)(1 * S_ + kt) * 32, 4096, mb);
        bulk_g2s(base + 16384,  g_vh + vbh + (size_t)(2 * t + 0) * DK_ * 32, 4096, mb);
        bulk_g2s(base + 20480,  g_vh + vbh + (size_t)(2 * t + 1) * DK_ * 32, 4096, mb);
        bulk_g2s(base + 24576,  g_vl + vbh + (size_t)(2 * t + 0) * DK_ * 32, 4096, mb);
        bulk_g2s(base + 28672,  g_vl + vbh + (size_t)(2 * t + 1) * DK_ * 32, 4096, mb);
    };

    if (tid == 0) issue(0);

#pragma unroll
    for (int i = 0; i < S_ / 256; i++)
        smadd[tid + i * 256] = (mask[b * S_ + tid + i * 256] == 0) ? -1e30f : 0.f;

    const size_t qoff = (size_t)bh * S_ * DK_;
    uint32_t aqh[4][4], aql[4][4];
#pragma unroll
    for (int ks = 0; ks < 4; ks++) {
        const int c0 = ks * 16 + 2 * tg;
        const size_t r0 = qoff + (size_t)(qrow0 + g) * DK_;
        const size_t r1 = qoff + (size_t)(qrow0 + g + 8) * DK_;
        aqh[ks][0] = *reinterpret_cast<const uint32_t*>(g_qh + r0 + c0);
        aqh[ks][1] = *reinterpret_cast<const uint32_t*>(g_qh + r1 + c0);
        aqh[ks][2] = *reinterpret_cast<const uint32_t*>(g_qh + r0 + c0 + 8);
        aqh[ks][3] = *reinterpret_cast<const uint32_t*>(g_qh + r1 + c0 + 8);
        aql[ks][0] = *reinterpret_cast<const uint32_t*>(g_ql + r0 + c0);
        aql[ks][1] = *reinterpret_cast<const uint32_t*>(g_ql + r1 + c0);
        aql[ks][2] = *reinterpret_cast<const uint32_t*>(g_ql + r0 + c0 + 8);
        aql[ks][3] = *reinterpret_cast<const uint32_t*>(g_ql + r1 + c0 + 8);
    }

    float accO[8][4];
#pragma unroll
    for (int i = 0; i < 8; i++)
#pragma unroll
        for (int j = 0; j < 4; j++) accO[i][j] = 0.f;

    float sum0 = 0.f, sum1 = 0.f;

    const int NTILES = S_ / 64;
    for (int t = 0; t < NTILES; t++) {
        const int kt = t * 64;
        if (t + 1 < NTILES) {
            __syncthreads();
            if (tid == 0) issue(t + 1);
        }
        MBAR_WAIT((t & 1) ? mb1 : mb0, (t >> 1) & 1);

        const uint32_t base = smb + 128 + (uint32_t)(t & 1) * ATB;
        const uint32_t bKh = base;
        const uint32_t bKl = base + 8192;
        const uint32_t bVh = base + 16384;
        const uint32_t bVl = base + 24576;

        // ---- per 16-key group: QK -> softmax -> PV ----
#pragma unroll
        for (int kg = 0; kg < 4; kg++) {
            // QK for this key group (keys kg*16 .. kg*16+15)
            float acc0[4], acc1[4];
#pragma unroll
            for (int j = 0; j < 4; j++) { acc0[j] = 0.f; acc1[j] = 0.f; }

#pragma unroll
            for (int ks = 0; ks < 4; ks++) {
                const int row = kg * 16 + rrB;             // key row within tile
                const int kdk = ks * 16 + khB * 8;          // dk
                const int sc = ((kdk >> 3) & 3) ^ ((row >> 1) & 3);
                const uint32_t off = (uint32_t)((kdk >> 5) * 4096 + row * 64 + sc * 16);
                uint32_t kh4[4], kl4[4];
                ldsm4(kh4, bKh + off);
                ldsm4(kl4, bKl + off);
                mma16816(acc0, aqh[ks], &kh4[0]);
                mma16816(acc1, aqh[ks], &kh4[2]);
                mma16816(acc0, aqh[ks], &kl4[0]);
                mma16816(acc1, aqh[ks], &kl4[2]);
                mma16816(acc0, aql[ks], &kh4[0]);
                mma16816(acc1, aql[ks], &kh4[2]);
            }

            // softmax (fixed-base) + hi/lo pack for this group
            uint32_t ph[4], pl[4];
            {
                const int nt0 = 2 * kg;
                const float ma0 = smadd[kt + nt0 * 8 + 2 * tg];
                const float mb_ = smadd[kt + nt0 * 8 + 2 * tg + 1];
                const float p0 = fast_exp2(acc0[0] + ma0);
                const float p1 = fast_exp2(acc0[1] + mb_);
                const float p2 = fast_exp2(acc0[2] + ma0);
                const float p3 = fast_exp2(acc0[3] + mb_);
                sum0 += p0 + p1;
                sum1 += p2 + p3;
                const uint32_t h01 = pack_bf16(p0, p1);
                const uint32_t h23 = pack_bf16(p2, p3);
                const float q0 = p0 - __uint_as_float(h01 << 16);
                const float q1 = p1 - __uint_as_float(h01 & 0xffff0000u);
                const float q2 = p2 - __uint_as_float(h23 << 16);
                const float q3 = p3 - __uint_as_float(h23 & 0xffff0000u);
                ph[0] = h01;
                ph[1] = h23;
                pl[0] = pack_bf16(q0, q1);
                pl[1] = pack_bf16(q2, q3);

                const float ma1 = smadd[kt + (nt0 + 1) * 8 + 2 * tg];
                const float mb1_ = smadd[kt + (nt0 + 1) * 8 + 2 * tg + 1];
                const float p4 = fast_exp2(acc1[0] + ma1);
                const float p5 = fast_exp2(acc1[1] + mb1_);
                const float p6 = fast_exp2(acc1[2] + ma1);
                const float p7 = fast_exp2(acc1[3] + mb1_);
                sum0 += p4 + p5;
                sum1 += p6 + p7;
                const uint32_t h45 = pack_bf16(p4, p5);
                const uint32_t h67 = pack_bf16(p6, p7);
                const float q4 = p4 - __uint_as_float(h45 << 16);
                const float q5 = p5 - __uint_as_float(h45 & 0xffff0000u);
                const float q6 = p6 - __uint_as_float(h67 << 16);
                const float q7 = p7 - __uint_as_float(h67 & 0xffff0000u);
                ph[2] = h45;
                ph[3] = h67;
                pl[2] = pack_bf16(q4, q5);
                pl[3] = pack_bf16(q6, q7);
            }

            // PV for this key group
#pragma unroll
            for (int ntp = 0; ntp < 4; ntp++) {
                const int row = ntp * 16 + rrB;             // dk row
                const int kss = kg * 16 + khB * 8;          // s within tile
                const int sc = ((kss >> 3) & 3) ^ ((row >> 1) & 3);
                const uint32_t off = (uint32_t)((kss >> 5) * 4096 + row * 64 + sc * 16);
                uint32_t vh4[4], vl4[4];
                ldsm4(vh4, bVh + off);
                ldsm4(vl4, bVl + off);
                mma16816(accO[2 * ntp],     ph, &vh4[0]);
                mma16816(accO[2 * ntp + 1], ph, &vh4[2]);
                mma16816(accO[2 * ntp],     ph, &vl4[0]);
                mma16816(accO[2 * ntp + 1], ph, &vl4[2]);
                mma16816(accO[2 * ntp],     pl, &vh4[0]);
                mma16816(accO[2 * ntp + 1], pl, &vh4[2]);
            }
        }
    }

    sum0 += __shfl_xor_sync(0xffffffffu, sum0, 1);
    sum0 += __shfl_xor_sync(0xffffffffu, sum0, 2);
    sum1 += __shfl_xor_sync(0xffffffffu, sum1, 1);
    sum1 += __shfl_xor_sync(0xffffffffu, sum1, 2);

    const float i0 = 1.f / sum0;
    const float i1 = 1.f / sum1;
    const int m0 = b * S_ + qrow0 + g;
    const int m1 = m0 + 8;
#pragma unroll
    for (int nt2 = 0; nt2 < 8; nt2++) {
        const int col = h * DK_ + nt2 * 8 + 2 * tg;
        float vx0 = accO[nt2][0] * i0, vy0 = accO[nt2][1] * i0;
        float vx1 = accO[nt2][2] * i1, vy1 = accO[nt2][3] * i1;
        __nv_bfloat16 hx, lx, hy, ly;
        const size_t p0 = tm_idx(m0, col, M_);
        split1(vx0, hx, lx); split1(vy0, hy, ly);
        *reinterpret_cast<uint32_t*>(g_Ah[0] + p0) =
            ((uint32_t)__bfloat16_as_ushort(hy) << 16) | __bfloat16_as_ushort(hx);
        *reinterpret_cast<uint32_t*>(g_Al[0] + p0) =
            ((uint32_t)__bfloat16_as_ushort(ly) << 16) | __bfloat16_as_ushort(lx);
        const size_t p1 = tm_idx(m1, col, M_);
        split1(vx1, hx, lx); split1(vy1, hy, ly);
        *reinterpret_cast<uint32_t*>(g_Ah[0] + p1) =
            ((uint32_t)__bfloat16_as_ushort(hy) << 16) | __bfloat16_as_ushort(hx);
        *reinterpret_cast<uint32_t*>(g_Al[0] + p1) =
            ((uint32_t)__bfloat16_as_ushort(ly) << 16) | __bfloat16_as_ushort(lx);
    }
}

// ---------------------------------------------------------------------------
// Launch
// ---------------------------------------------------------------------------
extern "C" void kernel_launch(void* const* d_in, const int* in_sizes, int n_in,
                              void* d_out, int out_size)
{
    const float* query = (const float*)d_in[0];
    const float* key   = (const float*)d_in[1];
    const float* value = (const float*)d_in[2];
    const int*   mask  = (const int*)  d_in[3];
    const float* Wq = (const float*)d_in[4];
    const float* bq = (const float*)d_in[5];
    const float* Wk = (const float*)d_in[6];
    const float* bk = (const float*)d_in[7];
    const float* Wv = (const float*)d_in[8];
    const float* bv = (const float*)d_in[9];
    const float* Wo = (const float*)d_in[10];
    const float* bo = (const float*)d_in[11];
    float* out = (float*)d_out;

    cudaFuncSetAttribute(gemm_tc<1>, cudaFuncAttributeMaxDynamicSharedMemorySize, GEMM_SMEM);
    cudaFuncSetAttribute(gemm_tc<0>, cudaFuncAttributeMaxDynamicSharedMemorySize, GEMM_SMEM);
    cudaFuncSetAttribute(attn_tc,    cudaFuncAttributeMaxDynamicSharedMemorySize, ATTN_SMEM);

    dim3 wtg(D_ / 32, D_ / 32, 4);
    split_wt_all<<<wtg, dim3(32, 8)>>>(Wq, Wk, Wv, Wo);
    dim3 sag((M_ * D_ / 4) / 256, 3);
    split_act_all<<<sag, 256>>>(query, key, value);

    dim3 gqkv(D_ / 128, M_ / 128, 3);
    gemm_tc<1><<<gqkv, 256, GEMM_SMEM>>>(bq, bk, bv, nullptr);

    dim3 agrid(S_ / 128, B_ * H_);
    attn_tc<<<agrid, 256, ATTN_SMEM>>>(mask);

    dim3 gout(D_ / 128, M_ / 128);
    gemm_tc<0><<<gout, 256, GEMM_SMEM>>>(bo, nullptr, nullptr, out);
}